// round 1
// baseline (speedup 1.0000x reference)
#include <cuda_runtime.h>
#include <cuda_bf16.h>
#include <math.h>

// Problem constants (fixed shapes per reference)
#define S_LEN   4096
#define D_MODEL 1024
#define NHEADS  16
#define D_K     64

// ---------------------------------------------------------------------------
// Scratch (device globals; no allocation allowed)
// ---------------------------------------------------------------------------
__device__ float g_Q[S_LEN * D_MODEL];
__device__ float g_K[S_LEN * D_MODEL];
__device__ float g_V[S_LEN * D_MODEL];
__device__ float g_C[S_LEN * D_MODEL];

// ---------------------------------------------------------------------------
// GEMM: C[M,N] = A[M,K] * B[N,K]^T   (both A and B row-major, K contiguous)
// Tiles: 128x128x8, 256 threads, 8x8 per-thread microtile.
// Smem rows padded to 132 floats: conflict-free transposed stores AND
// 16B-aligned (132*4 = 528 bytes, multiple of 16) float4 fragment loads.
// ---------------------------------------------------------------------------
#define GBM 128
#define GBN 128
#define GBK 8
#define GPAD 132

__global__ __launch_bounds__(256, 2) void gemm_nt_kernel(
    const float* __restrict__ A,
    const float* __restrict__ B,
    float* __restrict__ C,
    int M, int N, int K)
{
    __shared__ float As[GBK][GPAD];
    __shared__ float Bs[GBK][GPAD];

    const int tid = threadIdx.x;
    const int tx  = tid & 15;    // 0..15 -> N dimension
    const int ty  = tid >> 4;    // 0..15 -> M dimension
    const int bm  = blockIdx.y * GBM;
    const int bn  = blockIdx.x * GBN;

    // Global staging: each thread loads one float4 of A and one of B per tile.
    const int lr = tid >> 1;          // 0..127 : row within tile
    const int lc = (tid & 1) * 4;     // 0 or 4 : col within BK=8

    const float* Ag = A + (size_t)(bm + lr) * K + lc;
    const float* Bg = B + (size_t)(bn + lr) * K + lc;

    float4 a = *(const float4*)Ag;
    float4 b = *(const float4*)Bg;

    float acc[8][8];
#pragma unroll
    for (int i = 0; i < 8; i++)
#pragma unroll
        for (int j = 0; j < 8; j++) acc[i][j] = 0.0f;

    for (int kt = GBK; kt <= K; kt += GBK) {
        // Commit staged registers to smem (transposed: [k][m])
        As[lc + 0][lr] = a.x; As[lc + 1][lr] = a.y;
        As[lc + 2][lr] = a.z; As[lc + 3][lr] = a.w;
        Bs[lc + 0][lr] = b.x; Bs[lc + 1][lr] = b.y;
        Bs[lc + 2][lr] = b.z; Bs[lc + 3][lr] = b.w;
        __syncthreads();

        // Prefetch next tile while computing this one
        if (kt < K) {
            a = *(const float4*)(Ag + kt);
            b = *(const float4*)(Bg + kt);
        }

#pragma unroll
        for (int kk = 0; kk < GBK; kk++) {
            float4 a0 = *(const float4*)&As[kk][ty * 8];
            float4 a1 = *(const float4*)&As[kk][ty * 8 + 4];
            float4 b0 = *(const float4*)&Bs[kk][tx * 8];
            float4 b1 = *(const float4*)&Bs[kk][tx * 8 + 4];
            float ar[8] = {a0.x, a0.y, a0.z, a0.w, a1.x, a1.y, a1.z, a1.w};
            float br[8] = {b0.x, b0.y, b0.z, b0.w, b1.x, b1.y, b1.z, b1.w};
#pragma unroll
            for (int i = 0; i < 8; i++)
#pragma unroll
                for (int j = 0; j < 8; j++)
                    acc[i][j] += ar[i] * br[j];
        }
        __syncthreads();
    }

    // Epilogue: coalesced float4 stores
#pragma unroll
    for (int i = 0; i < 8; i++) {
        float* Cp = C + (size_t)(bm + ty * 8 + i) * N + bn + tx * 8;
        float4 c0 = make_float4(acc[i][0], acc[i][1], acc[i][2], acc[i][3]);
        float4 c1 = make_float4(acc[i][4], acc[i][5], acc[i][6], acc[i][7]);
        *(float4*)(Cp)     = c0;
        *(float4*)(Cp + 4) = c1;
    }
}

// ---------------------------------------------------------------------------
// Causal flash attention, fp32. One thread per query row; 128 rows per CTA.
// Q/K/V layout: [S, D_MODEL] with head h occupying columns [h*64, h*64+64).
// Online softmax with lazy rescale: rescale acc only when the running max
// changes (rare -> the 64-FMA rescale costs ~0 amortized).
// ---------------------------------------------------------------------------
#define FBM 128   // query rows per block (== threads per block)
#define FBK 64    // key tile

__global__ __launch_bounds__(128) void flash_attn_kernel(
    const float* __restrict__ Q,
    const float* __restrict__ K,
    const float* __restrict__ V,
    float* __restrict__ O)
{
    __shared__ float Ks[FBK][D_K];
    __shared__ float Vs[FBK][D_K];

    const int h     = blockIdx.y;
    const int q0    = blockIdx.x * FBM;
    const int tid   = threadIdx.x;
    const int q_row = q0 + tid;

    // Load this thread's query row into registers
    float q[D_K];
    const float* qp = Q + (size_t)q_row * D_MODEL + h * D_K;
#pragma unroll
    for (int d4 = 0; d4 < 16; d4++) {
        float4 v = *(const float4*)(qp + d4 * 4);
        q[d4 * 4 + 0] = v.x; q[d4 * 4 + 1] = v.y;
        q[d4 * 4 + 2] = v.z; q[d4 * 4 + 3] = v.w;
    }

    float m = -1e30f;
    float l = 0.0f;
    float acc[D_K];
#pragma unroll
    for (int d = 0; d < D_K; d++) acc[d] = 0.0f;

    const int kend = q0 + FBM;   // causal: keys strictly within [0, q0+FBM)
    const float inv_scale = 0.125f;  // 1/sqrt(64)

    for (int k0 = 0; k0 < kend; k0 += FBK) {
        // Cooperative tile load: 64x64 floats each for K and V
#pragma unroll
        for (int it = 0; it < 8; it++) {
            int idx = tid + it * 128;      // 0..1023 (float4 index)
            int r   = idx >> 4;
            int c4  = (idx & 15) * 4;
            *(float4*)&Ks[r][c4] =
                *(const float4*)(K + (size_t)(k0 + r) * D_MODEL + h * D_K + c4);
            *(float4*)&Vs[r][c4] =
                *(const float4*)(V + (size_t)(k0 + r) * D_MODEL + h * D_K + c4);
        }
        __syncthreads();

        int jmax = q_row - k0 + 1;           // number of unmasked keys in tile
        if (jmax > FBK) jmax = FBK;

        for (int j = 0; j < jmax; j++) {
            const float4* kr = (const float4*)Ks[j];
            float s0 = 0.f, s1 = 0.f, s2 = 0.f, s3 = 0.f;
#pragma unroll
            for (int d4 = 0; d4 < 16; d4++) {
                float4 kv = kr[d4];
                s0 += q[d4 * 4 + 0] * kv.x;
                s1 += q[d4 * 4 + 1] * kv.y;
                s2 += q[d4 * 4 + 2] * kv.z;
                s3 += q[d4 * 4 + 3] * kv.w;
            }
            float s = ((s0 + s1) + (s2 + s3)) * inv_scale;

            if (s > m) {   // rare: running-max update -> rescale accumulator
                float sc = __expf(m - s);
                l *= sc;
#pragma unroll
                for (int d = 0; d < D_K; d++) acc[d] *= sc;
                m = s;
            }
            float p = __expf(s - m);
            l += p;
            const float4* vr = (const float4*)Vs[j];
#pragma unroll
            for (int d4 = 0; d4 < 16; d4++) {
                float4 vv = vr[d4];
                acc[d4 * 4 + 0] += p * vv.x;
                acc[d4 * 4 + 1] += p * vv.y;
                acc[d4 * 4 + 2] += p * vv.z;
                acc[d4 * 4 + 3] += p * vv.w;
            }
        }
        __syncthreads();
    }

    float inv = 1.0f / l;
    float* op = O + (size_t)q_row * D_MODEL + h * D_K;
#pragma unroll
    for (int d4 = 0; d4 < 16; d4++) {
        float4 o;
        o.x = acc[d4 * 4 + 0] * inv;
        o.y = acc[d4 * 4 + 1] * inv;
        o.z = acc[d4 * 4 + 2] * inv;
        o.w = acc[d4 * 4 + 3] * inv;
        *(float4*)(op + d4 * 4) = o;
    }
}

// ---------------------------------------------------------------------------
// Launch
// ---------------------------------------------------------------------------
extern "C" void kernel_launch(void* const* d_in, const int* in_sizes, int n_in,
                              void* d_out, int out_size)
{
    const float* x   = (const float*)d_in[0];
    const float* W_q = (const float*)d_in[1];
    const float* W_k = (const float*)d_in[2];
    const float* W_v = (const float*)d_in[3];
    const float* W_o = (const float*)d_in[4];
    float* out = (float*)d_out;

    // Resolve scratch symbol addresses once (non-stream API; capture-safe,
    // deterministic — no work is gated on this).
    static float* pQ = nullptr;
    static float* pK = nullptr;
    static float* pV = nullptr;
    static float* pC = nullptr;
    if (pQ == nullptr) {
        cudaGetSymbolAddress((void**)&pQ, g_Q);
        cudaGetSymbolAddress((void**)&pK, g_K);
        cudaGetSymbolAddress((void**)&pV, g_V);
        cudaGetSymbolAddress((void**)&pC, g_C);
    }

    dim3 ggrid(D_MODEL / GBN, S_LEN / GBM);   // (8, 32)
    dim3 gblk(256);

    gemm_nt_kernel<<<ggrid, gblk>>>(x, W_q, pQ, S_LEN, D_MODEL, D_MODEL);
    gemm_nt_kernel<<<ggrid, gblk>>>(x, W_k, pK, S_LEN, D_MODEL, D_MODEL);
    gemm_nt_kernel<<<ggrid, gblk>>>(x, W_v, pV, S_LEN, D_MODEL, D_MODEL);

    dim3 agrid(S_LEN / FBM, NHEADS);          // (32, 16)
    flash_attn_kernel<<<agrid, 128>>>(pQ, pK, pV, pC);

    gemm_nt_kernel<<<ggrid, gblk>>>(pC, W_o, out, S_LEN, D_MODEL, D_MODEL);
}

// round 3
// speedup vs baseline: 1.3987x; 1.3987x over previous
#include <cuda_runtime.h>
#include <cuda_bf16.h>
#include <math.h>
#include <stdint.h>

// Problem constants (fixed shapes per reference)
#define S_LEN   4096
#define D_MODEL 1024
#define NHEADS  16
#define D_K     64

// ---------------------------------------------------------------------------
// Scratch (device globals; no allocation allowed)
// ---------------------------------------------------------------------------
__device__ float g_Q[S_LEN * D_MODEL];
__device__ float g_K[S_LEN * D_MODEL];
__device__ float g_V[S_LEN * D_MODEL];
__device__ float g_C[S_LEN * D_MODEL];

__device__ __nv_bfloat16 g_xh[S_LEN * D_MODEL];
__device__ __nv_bfloat16 g_xl[S_LEN * D_MODEL];
__device__ __nv_bfloat16 g_ch[S_LEN * D_MODEL];
__device__ __nv_bfloat16 g_cl[S_LEN * D_MODEL];
__device__ __nv_bfloat16 g_wqh[D_MODEL * D_MODEL];
__device__ __nv_bfloat16 g_wql[D_MODEL * D_MODEL];
__device__ __nv_bfloat16 g_wkh[D_MODEL * D_MODEL];
__device__ __nv_bfloat16 g_wkl[D_MODEL * D_MODEL];
__device__ __nv_bfloat16 g_wvh[D_MODEL * D_MODEL];
__device__ __nv_bfloat16 g_wvl[D_MODEL * D_MODEL];
__device__ __nv_bfloat16 g_woh[D_MODEL * D_MODEL];
__device__ __nv_bfloat16 g_wol[D_MODEL * D_MODEL];

// ---------------------------------------------------------------------------
// PTX helpers (base sm_80+ features only — the build targets compute_103,
// which rejects all tcgen05/TMEM arch-accelerated instructions)
// ---------------------------------------------------------------------------
__device__ __forceinline__ uint32_t smem_u32(const void* p) {
    uint32_t a;
    asm("{ .reg .u64 t; cvta.to.shared.u64 t, %1; cvt.u32.u64 %0, t; }"
        : "=r"(a) : "l"(p));
    return a;
}

__device__ __forceinline__ void cp_async16(uint32_t smem_dst, const void* gmem_src) {
    asm volatile("cp.async.cg.shared.global [%0], [%1], 16;\n"
                 :: "r"(smem_dst), "l"(gmem_src));
}

__device__ __forceinline__ void ldsm_x4(uint32_t* r, uint32_t addr) {
    asm volatile("ldmatrix.sync.aligned.m8n8.x4.shared.b16 {%0,%1,%2,%3}, [%4];"
                 : "=r"(r[0]), "=r"(r[1]), "=r"(r[2]), "=r"(r[3]) : "r"(addr));
}

__device__ __forceinline__ void mma_16816(float* d, const uint32_t* a, const uint32_t* b) {
    asm volatile(
        "mma.sync.aligned.m16n8k16.row.col.f32.bf16.bf16.f32 "
        "{%0,%1,%2,%3}, {%4,%5,%6,%7}, {%8,%9}, {%0,%1,%2,%3};"
        : "+f"(d[0]), "+f"(d[1]), "+f"(d[2]), "+f"(d[3])
        : "r"(a[0]), "r"(a[1]), "r"(a[2]), "r"(a[3]), "r"(b[0]), "r"(b[1]));
}

// ---------------------------------------------------------------------------
// Split fp32 -> bf16 hi/lo  (hi = bf16(x), lo = bf16(x - float(hi)))
// ---------------------------------------------------------------------------
__global__ void split_bf16_kernel(const float* __restrict__ in,
                                  __nv_bfloat16* __restrict__ hi,
                                  __nv_bfloat16* __restrict__ lo, int n4)
{
    int i = blockIdx.x * blockDim.x + threadIdx.x;
    if (i >= n4) return;
    float4 v = ((const float4*)in)[i];
    __nv_bfloat16 h0 = __float2bfloat16(v.x);
    __nv_bfloat16 h1 = __float2bfloat16(v.y);
    __nv_bfloat16 h2 = __float2bfloat16(v.z);
    __nv_bfloat16 h3 = __float2bfloat16(v.w);
    __nv_bfloat16 l0 = __float2bfloat16(v.x - __bfloat162float(h0));
    __nv_bfloat16 l1 = __float2bfloat16(v.y - __bfloat162float(h1));
    __nv_bfloat16 l2 = __float2bfloat16(v.z - __bfloat162float(h2));
    __nv_bfloat16 l3 = __float2bfloat16(v.w - __bfloat162float(h3));
    ((__nv_bfloat162*)hi)[i * 2 + 0] = __nv_bfloat162(h0, h1);
    ((__nv_bfloat162*)hi)[i * 2 + 1] = __nv_bfloat162(h2, h3);
    ((__nv_bfloat162*)lo)[i * 2 + 0] = __nv_bfloat162(l0, l1);
    ((__nv_bfloat162*)lo)[i * 2 + 1] = __nv_bfloat162(l2, l3);
}

// ---------------------------------------------------------------------------
// Tensor-core GEMM via mma.sync (HMMA, bf16, fp32 acc):
//   C[4096,1024] = Ahi*Bhi^T + Ahi*Blo^T + Alo*Bhi^T
// A: [4096,1024] bf16 K-major, B: [1024,1024] bf16 K-major (torch weight).
// CTA 128x128 tile, 8 warps (each 32x64), BK=32 double-buffered cp.async.
// Smem rows 80B (64B payload + 16B pad) -> conflict-free ldmatrix,
// no swizzle. 96 chunks: term = chunk/32 selects (hi,hi)/(hi,lo)/(lo,hi).
// ---------------------------------------------------------------------------
#define GK     1024
#define GBK    32
#define ROWB   80
#define NCHUNK 96

__device__ __forceinline__ void load_chunk(
    const __nv_bfloat16* __restrict__ A, const __nv_bfloat16* __restrict__ B,
    int bm, int bn, int k0, uint32_t sa, uint32_t sb, int tid)
{
    // 128 rows x 64 bytes each for A and B; 512 x 16B per tile; 2 per thread.
#pragma unroll
    for (int t = 0; t < 2; t++) {
        int u = tid + t * 256;
        int r = u >> 2;
        int c = (u & 3) * 16;
        cp_async16(sa + r * ROWB + c,
                   (const char*)(A + (size_t)(bm + r) * GK + k0) + c);
        cp_async16(sb + r * ROWB + c,
                   (const char*)(B + (size_t)(bn + r) * GK + k0) + c);
    }
    asm volatile("cp.async.commit_group;\n" ::: "memory");
}

__global__ __launch_bounds__(256, 2) void gemm_mma_kernel(
    const __nv_bfloat16* __restrict__ A_hi, const __nv_bfloat16* __restrict__ A_lo,
    const __nv_bfloat16* __restrict__ B_hi, const __nv_bfloat16* __restrict__ B_lo,
    float* __restrict__ C)
{
    __shared__ __align__(16) char sA[2][128 * ROWB];
    __shared__ __align__(16) char sB[2][128 * ROWB];

    const int tid  = threadIdx.x;
    const int lane = tid & 31;
    const int w    = tid >> 5;
    const int m_off = (w & 3) * 32;     // warp M offset in CTA tile
    const int n_off = (w >> 2) * 64;    // warp N offset in CTA tile
    const int bm = blockIdx.y * 128;
    const int bn = blockIdx.x * 128;

    float acc[2][8][4];
#pragma unroll
    for (int mt = 0; mt < 2; mt++)
#pragma unroll
        for (int nt = 0; nt < 8; nt++)
#pragma unroll
            for (int i = 0; i < 4; i++) acc[mt][nt][i] = 0.0f;

    // ldmatrix per-thread addressing
    // A 16x16 tile: t0-15 -> rows 0-15 @ col 0, t16-31 -> rows 0-15 @ col+16
    const int a_r = m_off + (lane & 15);
    const int a_c = 16 * (lane >> 4);
    // B pair of n-tiles: t0-7 n0-7@c0, t8-15 n0-7@c16, t16-23 n8-15@c0, t24-31 n8-15@c16
    const int b_r = n_off + (lane & 7) + 8 * (lane >> 4);
    const int b_c = 16 * ((lane >> 3) & 1);

    const uint32_t saw[2] = { smem_u32(sA[0]), smem_u32(sA[1]) };
    const uint32_t sbw[2] = { smem_u32(sB[0]), smem_u32(sB[1]) };

    // chunk -> operand sources (term = chunk/32)
    auto a_src = [&](int c) { return (c >> 5) < 2 ? A_hi : A_lo; };
    auto b_src = [&](int c) { return (c >> 5) == 1 ? B_lo : B_hi; };
    auto k_of  = [&](int c) { return (c & 31) * GBK; };

    load_chunk(a_src(0), b_src(0), bm, bn, k_of(0), saw[0], sbw[0], tid);

    for (int i = 0; i < NCHUNK; i++) {
        const int buf = i & 1;
        if (i + 1 < NCHUNK) {
            load_chunk(a_src(i + 1), b_src(i + 1), bm, bn, k_of(i + 1),
                       saw[buf ^ 1], sbw[buf ^ 1], tid);
            asm volatile("cp.async.wait_group 1;\n" ::: "memory");
        } else {
            asm volatile("cp.async.wait_group 0;\n" ::: "memory");
        }
        __syncthreads();

        const uint32_t ab = saw[buf];
        const uint32_t bb = sbw[buf];
#pragma unroll
        for (int ks = 0; ks < 2; ks++) {
            uint32_t a[2][4];
            uint32_t b[8][2];
#pragma unroll
            for (int mt = 0; mt < 2; mt++)
                ldsm_x4(a[mt], ab + (a_r + mt * 16) * ROWB + a_c + ks * 32);
#pragma unroll
            for (int ntp = 0; ntp < 4; ntp++) {
                uint32_t r[4];
                ldsm_x4(r, bb + (b_r + ntp * 16) * ROWB + b_c + ks * 32);
                b[2 * ntp + 0][0] = r[0]; b[2 * ntp + 0][1] = r[1];
                b[2 * ntp + 1][0] = r[2]; b[2 * ntp + 1][1] = r[3];
            }
#pragma unroll
            for (int mt = 0; mt < 2; mt++)
#pragma unroll
                for (int nt = 0; nt < 8; nt++)
                    mma_16816(acc[mt][nt], a[mt], b[nt]);
        }
        __syncthreads();
    }

    // Epilogue: direct float2 stores (acc layout: d0,d1 @ (g, 2q); d2,d3 @ (g+8, 2q))
    const int g = lane >> 2;
    const int q = lane & 3;
#pragma unroll
    for (int mt = 0; mt < 2; mt++) {
#pragma unroll
        for (int nt = 0; nt < 8; nt++) {
            int row = bm + m_off + mt * 16 + g;
            int col = bn + n_off + nt * 8 + q * 2;
            *(float2*)(C + (size_t)row * D_MODEL + col) =
                make_float2(acc[mt][nt][0], acc[mt][nt][1]);
            *(float2*)(C + (size_t)(row + 8) * D_MODEL + col) =
                make_float2(acc[mt][nt][2], acc[mt][nt][3]);
        }
    }
}

// ---------------------------------------------------------------------------
// Causal flash attention, fp32. One thread per query row; 128 rows per CTA.
// 4-key unrolled inner loop; reversed block order (heavy blocks first).
// ---------------------------------------------------------------------------
#define FBM 128
#define FBK 64

__global__ __launch_bounds__(128) void flash_attn_kernel(
    const float* __restrict__ Q,
    const float* __restrict__ K,
    const float* __restrict__ V,
    float* __restrict__ O)
{
    __shared__ float Ks[FBK][D_K];
    __shared__ float Vs[FBK][D_K];

    const int h     = blockIdx.y;
    const int q0    = (gridDim.x - 1 - blockIdx.x) * FBM;   // heavy blocks first
    const int tid   = threadIdx.x;
    const int q_row = q0 + tid;

    float q[D_K];
    const float* qp = Q + (size_t)q_row * D_MODEL + h * D_K;
#pragma unroll
    for (int d4 = 0; d4 < 16; d4++) {
        float4 v = *(const float4*)(qp + d4 * 4);
        q[d4 * 4 + 0] = v.x; q[d4 * 4 + 1] = v.y;
        q[d4 * 4 + 2] = v.z; q[d4 * 4 + 3] = v.w;
    }

    float m = -1e30f;
    float l = 0.0f;
    float acc[D_K];
#pragma unroll
    for (int d = 0; d < D_K; d++) acc[d] = 0.0f;

    const int kend = q0 + FBM;
    const float inv_scale = 0.125f;   // 1/sqrt(64)

    for (int k0 = 0; k0 < kend; k0 += FBK) {
#pragma unroll
        for (int it = 0; it < 8; it++) {
            int idx = tid + it * 128;
            int r   = idx >> 4;
            int c4  = (idx & 15) * 4;
            *(float4*)&Ks[r][c4] =
                *(const float4*)(K + (size_t)(k0 + r) * D_MODEL + h * D_K + c4);
            *(float4*)&Vs[r][c4] =
                *(const float4*)(V + (size_t)(k0 + r) * D_MODEL + h * D_K + c4);
        }
        __syncthreads();

        int jmax = q_row - k0 + 1;
        if (jmax > FBK) jmax = FBK;

        int j = 0;
        for (; j + 4 <= jmax; j += 4) {
            const float4* kr0 = (const float4*)Ks[j + 0];
            const float4* kr1 = (const float4*)Ks[j + 1];
            const float4* kr2 = (const float4*)Ks[j + 2];
            const float4* kr3 = (const float4*)Ks[j + 3];
            float s0 = 0.f, s1 = 0.f, s2 = 0.f, s3 = 0.f;
#pragma unroll
            for (int d4 = 0; d4 < 16; d4++) {
                float4 a = kr0[d4], b = kr1[d4], c = kr2[d4], e = kr3[d4];
                float q0v = q[d4 * 4 + 0], q1v = q[d4 * 4 + 1];
                float q2v = q[d4 * 4 + 2], q3v = q[d4 * 4 + 3];
                s0 += q0v * a.x; s1 += q0v * b.x; s2 += q0v * c.x; s3 += q0v * e.x;
                s0 += q1v * a.y; s1 += q1v * b.y; s2 += q1v * c.y; s3 += q1v * e.y;
                s0 += q2v * a.z; s1 += q2v * b.z; s2 += q2v * c.z; s3 += q2v * e.z;
                s0 += q3v * a.w; s1 += q3v * b.w; s2 += q3v * c.w; s3 += q3v * e.w;
            }
            s0 *= inv_scale; s1 *= inv_scale; s2 *= inv_scale; s3 *= inv_scale;
            float mx = fmaxf(fmaxf(s0, s1), fmaxf(s2, s3));
            if (mx > m) {
                float sc = __expf(m - mx);
                l *= sc;
#pragma unroll
                for (int d = 0; d < D_K; d++) acc[d] *= sc;
                m = mx;
            }
            float p0 = __expf(s0 - m);
            float p1 = __expf(s1 - m);
            float p2 = __expf(s2 - m);
            float p3 = __expf(s3 - m);
            l += (p0 + p1) + (p2 + p3);
            const float4* vr0 = (const float4*)Vs[j + 0];
            const float4* vr1 = (const float4*)Vs[j + 1];
            const float4* vr2 = (const float4*)Vs[j + 2];
            const float4* vr3 = (const float4*)Vs[j + 3];
#pragma unroll
            for (int d4 = 0; d4 < 16; d4++) {
                float4 a = vr0[d4], b = vr1[d4], c = vr2[d4], e = vr3[d4];
                acc[d4 * 4 + 0] += p0 * a.x + p1 * b.x + p2 * c.x + p3 * e.x;
                acc[d4 * 4 + 1] += p0 * a.y + p1 * b.y + p2 * c.y + p3 * e.y;
                acc[d4 * 4 + 2] += p0 * a.z + p1 * b.z + p2 * c.z + p3 * e.z;
                acc[d4 * 4 + 3] += p0 * a.w + p1 * b.w + p2 * c.w + p3 * e.w;
            }
        }
        for (; j < jmax; j++) {
            const float4* kr = (const float4*)Ks[j];
            float s0 = 0.f, s1 = 0.f, s2 = 0.f, s3 = 0.f;
#pragma unroll
            for (int d4 = 0; d4 < 16; d4++) {
                float4 kv = kr[d4];
                s0 += q[d4 * 4 + 0] * kv.x;
                s1 += q[d4 * 4 + 1] * kv.y;
                s2 += q[d4 * 4 + 2] * kv.z;
                s3 += q[d4 * 4 + 3] * kv.w;
            }
            float s = ((s0 + s1) + (s2 + s3)) * inv_scale;
            if (s > m) {
                float sc = __expf(m - s);
                l *= sc;
#pragma unroll
                for (int d = 0; d < D_K; d++) acc[d] *= sc;
                m = s;
            }
            float p = __expf(s - m);
            l += p;
            const float4* vr = (const float4*)Vs[j];
#pragma unroll
            for (int d4 = 0; d4 < 16; d4++) {
                float4 vv = vr[d4];
                acc[d4 * 4 + 0] += p * vv.x;
                acc[d4 * 4 + 1] += p * vv.y;
                acc[d4 * 4 + 2] += p * vv.z;
                acc[d4 * 4 + 3] += p * vv.w;
            }
        }
        __syncthreads();
    }

    float inv = 1.0f / l;
    float* op = O + (size_t)q_row * D_MODEL + h * D_K;
#pragma unroll
    for (int d4 = 0; d4 < 16; d4++) {
        float4 o;
        o.x = acc[d4 * 4 + 0] * inv;
        o.y = acc[d4 * 4 + 1] * inv;
        o.z = acc[d4 * 4 + 2] * inv;
        o.w = acc[d4 * 4 + 3] * inv;
        *(float4*)(op + d4 * 4) = o;
    }
}

// ---------------------------------------------------------------------------
// Launch
// ---------------------------------------------------------------------------
extern "C" void kernel_launch(void* const* d_in, const int* in_sizes, int n_in,
                              void* d_out, int out_size)
{
    const float* x   = (const float*)d_in[0];
    const float* W_q = (const float*)d_in[1];
    const float* W_k = (const float*)d_in[2];
    const float* W_v = (const float*)d_in[3];
    const float* W_o = (const float*)d_in[4];
    float* out = (float*)d_out;

    static float* pQ = nullptr;
    static float *pK, *pV, *pC;
    static __nv_bfloat16 *xh, *xl, *ch, *cl;
    static __nv_bfloat16 *wqh, *wql, *wkh, *wkl, *wvh, *wvl, *woh, *wol;
    if (pQ == nullptr) {
        cudaGetSymbolAddress((void**)&pK, g_K);
        cudaGetSymbolAddress((void**)&pV, g_V);
        cudaGetSymbolAddress((void**)&pC, g_C);
        cudaGetSymbolAddress((void**)&xh, g_xh);
        cudaGetSymbolAddress((void**)&xl, g_xl);
        cudaGetSymbolAddress((void**)&ch, g_ch);
        cudaGetSymbolAddress((void**)&cl, g_cl);
        cudaGetSymbolAddress((void**)&wqh, g_wqh);
        cudaGetSymbolAddress((void**)&wql, g_wql);
        cudaGetSymbolAddress((void**)&wkh, g_wkh);
        cudaGetSymbolAddress((void**)&wkl, g_wkl);
        cudaGetSymbolAddress((void**)&wvh, g_wvh);
        cudaGetSymbolAddress((void**)&wvl, g_wvl);
        cudaGetSymbolAddress((void**)&woh, g_woh);
        cudaGetSymbolAddress((void**)&wol, g_wol);
        cudaGetSymbolAddress((void**)&pQ, g_Q);   // last: publishes init
    }

    const int n_x4 = S_LEN * D_MODEL / 4;     // 1M float4s
    const int n_w4 = D_MODEL * D_MODEL / 4;   // 256K float4s
    split_bf16_kernel<<<(n_x4 + 255) / 256, 256>>>(x, xh, xl, n_x4);
    split_bf16_kernel<<<(n_w4 + 255) / 256, 256>>>(W_q, wqh, wql, n_w4);
    split_bf16_kernel<<<(n_w4 + 255) / 256, 256>>>(W_k, wkh, wkl, n_w4);
    split_bf16_kernel<<<(n_w4 + 255) / 256, 256>>>(W_v, wvh, wvl, n_w4);
    split_bf16_kernel<<<(n_w4 + 255) / 256, 256>>>(W_o, woh, wol, n_w4);

    dim3 ggrid(D_MODEL / 128, S_LEN / 128);   // (8, 32)
    gemm_mma_kernel<<<ggrid, 256>>>(xh, xl, wqh, wql, pQ);
    gemm_mma_kernel<<<ggrid, 256>>>(xh, xl, wkh, wkl, pK);
    gemm_mma_kernel<<<ggrid, 256>>>(xh, xl, wvh, wvl, pV);

    dim3 agrid(S_LEN / FBM, NHEADS);          // (32, 16)
    flash_attn_kernel<<<agrid, 128>>>(pQ, pK, pV, pC);

    split_bf16_kernel<<<(n_x4 + 255) / 256, 256>>>(pC, ch, cl, n_x4);
    gemm_mma_kernel<<<ggrid, 256>>>(ch, cl, woh, wol, out);
}

// round 4
// speedup vs baseline: 3.5386x; 2.5300x over previous
#include <cuda_runtime.h>
#include <cuda_bf16.h>
#include <math.h>
#include <stdint.h>

// Problem constants (fixed shapes per reference)
#define S_LEN   4096
#define D_MODEL 1024
#define NHEADS  16
#define D_K     64

// ---------------------------------------------------------------------------
// Scratch (device globals; no allocation allowed)
// ---------------------------------------------------------------------------
__device__ __nv_bfloat16 g_xh[S_LEN * D_MODEL];
__device__ __nv_bfloat16 g_xl[S_LEN * D_MODEL];
__device__ __nv_bfloat16 g_ch[S_LEN * D_MODEL];
__device__ __nv_bfloat16 g_cl[S_LEN * D_MODEL];
__device__ __nv_bfloat16 g_Qh[S_LEN * D_MODEL];
__device__ __nv_bfloat16 g_Ql[S_LEN * D_MODEL];
__device__ __nv_bfloat16 g_Kh[S_LEN * D_MODEL];
__device__ __nv_bfloat16 g_Kl[S_LEN * D_MODEL];
__device__ __nv_bfloat16 g_Vh[S_LEN * D_MODEL];
__device__ __nv_bfloat16 g_Vl[S_LEN * D_MODEL];
__device__ __nv_bfloat16 g_wqh[D_MODEL * D_MODEL];
__device__ __nv_bfloat16 g_wql[D_MODEL * D_MODEL];
__device__ __nv_bfloat16 g_wkh[D_MODEL * D_MODEL];
__device__ __nv_bfloat16 g_wkl[D_MODEL * D_MODEL];
__device__ __nv_bfloat16 g_wvh[D_MODEL * D_MODEL];
__device__ __nv_bfloat16 g_wvl[D_MODEL * D_MODEL];
__device__ __nv_bfloat16 g_woh[D_MODEL * D_MODEL];
__device__ __nv_bfloat16 g_wol[D_MODEL * D_MODEL];

// ---------------------------------------------------------------------------
// PTX helpers (base sm_80+ features only — build targets plain compute_103)
// ---------------------------------------------------------------------------
__device__ __forceinline__ uint32_t smem_u32(const void* p) {
    uint32_t a;
    asm("{ .reg .u64 t; cvta.to.shared.u64 t, %1; cvt.u32.u64 %0, t; }"
        : "=r"(a) : "l"(p));
    return a;
}

__device__ __forceinline__ void cp_async16(uint32_t smem_dst, const void* gmem_src) {
    asm volatile("cp.async.cg.shared.global [%0], [%1], 16;\n"
                 :: "r"(smem_dst), "l"(gmem_src));
}

__device__ __forceinline__ void ldsm_x4(uint32_t* r, uint32_t addr) {
    asm volatile("ldmatrix.sync.aligned.m8n8.x4.shared.b16 {%0,%1,%2,%3}, [%4];"
                 : "=r"(r[0]), "=r"(r[1]), "=r"(r[2]), "=r"(r[3]) : "r"(addr));
}

__device__ __forceinline__ void ldsm_x4_t(uint32_t* r, uint32_t addr) {
    asm volatile("ldmatrix.sync.aligned.m8n8.x4.trans.shared.b16 {%0,%1,%2,%3}, [%4];"
                 : "=r"(r[0]), "=r"(r[1]), "=r"(r[2]), "=r"(r[3]) : "r"(addr));
}

__device__ __forceinline__ void mma_16816(float* d, const uint32_t* a, const uint32_t* b) {
    asm volatile(
        "mma.sync.aligned.m16n8k16.row.col.f32.bf16.bf16.f32 "
        "{%0,%1,%2,%3}, {%4,%5,%6,%7}, {%8,%9}, {%0,%1,%2,%3};"
        : "+f"(d[0]), "+f"(d[1]), "+f"(d[2]), "+f"(d[3])
        : "r"(a[0]), "r"(a[1]), "r"(a[2]), "r"(a[3]), "r"(b[0]), "r"(b[1]));
}

__device__ __forceinline__ float fast_exp2(float x) {
    float r; asm("ex2.approx.f32 %0, %1;" : "=f"(r) : "f"(x)); return r;
}

// pack two fp32 -> bf16x2 (x in low half, y in high half)
__device__ __forceinline__ uint32_t pack_bf(float x, float y) {
    uint32_t r;
    asm("cvt.rn.bf16x2.f32 %0, %1, %2;" : "=r"(r) : "f"(y), "f"(x));
    return r;
}
__device__ __forceinline__ float bf_lo(uint32_t r) { return __uint_as_float(r << 16); }
__device__ __forceinline__ float bf_hi(uint32_t r) { return __uint_as_float(r & 0xffff0000u); }

// ---------------------------------------------------------------------------
// Split fp32 -> bf16 hi/lo  (hi = bf16(x), lo = bf16(x - float(hi)))
// ---------------------------------------------------------------------------
__global__ void split_bf16_kernel(const float* __restrict__ in,
                                  __nv_bfloat16* __restrict__ hi,
                                  __nv_bfloat16* __restrict__ lo, int n4)
{
    int i = blockIdx.x * blockDim.x + threadIdx.x;
    if (i >= n4) return;
    float4 v = ((const float4*)in)[i];
    uint32_t h01 = pack_bf(v.x, v.y);
    uint32_t h23 = pack_bf(v.z, v.w);
    uint32_t l01 = pack_bf(v.x - bf_lo(h01), v.y - bf_hi(h01));
    uint32_t l23 = pack_bf(v.z - bf_lo(h23), v.w - bf_hi(h23));
    ((uint32_t*)hi)[i * 2 + 0] = h01;
    ((uint32_t*)hi)[i * 2 + 1] = h23;
    ((uint32_t*)lo)[i * 2 + 0] = l01;
    ((uint32_t*)lo)[i * 2 + 1] = l23;
}

// ---------------------------------------------------------------------------
// Tensor-core GEMM via mma.sync (HMMA, bf16, fp32 acc):
//   C[4096,1024] = Ahi*Bhi^T + Ahi*Blo^T + Alo*Bhi^T
// Epilogue: if Ch != null, write bf16 hi/lo pair; else fp32 Cf.
// ---------------------------------------------------------------------------
#define GK     1024
#define GBK    32
#define ROWB   80
#define NCHUNK 96

__device__ __forceinline__ void load_chunk(
    const __nv_bfloat16* __restrict__ A, const __nv_bfloat16* __restrict__ B,
    int bm, int bn, int k0, uint32_t sa, uint32_t sb, int tid)
{
#pragma unroll
    for (int t = 0; t < 2; t++) {
        int u = tid + t * 256;
        int r = u >> 2;
        int c = (u & 3) * 16;
        cp_async16(sa + r * ROWB + c,
                   (const char*)(A + (size_t)(bm + r) * GK + k0) + c);
        cp_async16(sb + r * ROWB + c,
                   (const char*)(B + (size_t)(bn + r) * GK + k0) + c);
    }
    asm volatile("cp.async.commit_group;\n" ::: "memory");
}

__global__ __launch_bounds__(256, 2) void gemm_mma_kernel(
    const __nv_bfloat16* __restrict__ A_hi, const __nv_bfloat16* __restrict__ A_lo,
    const __nv_bfloat16* __restrict__ B_hi, const __nv_bfloat16* __restrict__ B_lo,
    float* __restrict__ Cf,
    __nv_bfloat16* __restrict__ Ch, __nv_bfloat16* __restrict__ Cl)
{
    __shared__ __align__(16) char sA[2][128 * ROWB];
    __shared__ __align__(16) char sB[2][128 * ROWB];

    const int tid  = threadIdx.x;
    const int lane = tid & 31;
    const int w    = tid >> 5;
    const int m_off = (w & 3) * 32;
    const int n_off = (w >> 2) * 64;
    const int bm = blockIdx.y * 128;
    const int bn = blockIdx.x * 128;

    float acc[2][8][4];
#pragma unroll
    for (int mt = 0; mt < 2; mt++)
#pragma unroll
        for (int nt = 0; nt < 8; nt++)
#pragma unroll
            for (int i = 0; i < 4; i++) acc[mt][nt][i] = 0.0f;

    const int a_r = m_off + (lane & 15);
    const int a_c = 16 * (lane >> 4);
    const int b_r = n_off + (lane & 7) + 8 * (lane >> 4);
    const int b_c = 16 * ((lane >> 3) & 1);

    const uint32_t saw[2] = { smem_u32(sA[0]), smem_u32(sA[1]) };
    const uint32_t sbw[2] = { smem_u32(sB[0]), smem_u32(sB[1]) };

    auto a_src = [&](int c) { return (c >> 5) < 2 ? A_hi : A_lo; };
    auto b_src = [&](int c) { return (c >> 5) == 1 ? B_lo : B_hi; };
    auto k_of  = [&](int c) { return (c & 31) * GBK; };

    load_chunk(a_src(0), b_src(0), bm, bn, k_of(0), saw[0], sbw[0], tid);

    for (int i = 0; i < NCHUNK; i++) {
        const int buf = i & 1;
        if (i + 1 < NCHUNK) {
            load_chunk(a_src(i + 1), b_src(i + 1), bm, bn, k_of(i + 1),
                       saw[buf ^ 1], sbw[buf ^ 1], tid);
            asm volatile("cp.async.wait_group 1;\n" ::: "memory");
        } else {
            asm volatile("cp.async.wait_group 0;\n" ::: "memory");
        }
        __syncthreads();

        const uint32_t ab = saw[buf];
        const uint32_t bb = sbw[buf];
#pragma unroll
        for (int ks = 0; ks < 2; ks++) {
            uint32_t a[2][4];
            uint32_t b[8][2];
#pragma unroll
            for (int mt = 0; mt < 2; mt++)
                ldsm_x4(a[mt], ab + (a_r + mt * 16) * ROWB + a_c + ks * 32);
#pragma unroll
            for (int ntp = 0; ntp < 4; ntp++) {
                uint32_t r[4];
                ldsm_x4(r, bb + (b_r + ntp * 16) * ROWB + b_c + ks * 32);
                b[2 * ntp + 0][0] = r[0]; b[2 * ntp + 0][1] = r[1];
                b[2 * ntp + 1][0] = r[2]; b[2 * ntp + 1][1] = r[3];
            }
#pragma unroll
            for (int mt = 0; mt < 2; mt++)
#pragma unroll
                for (int nt = 0; nt < 8; nt++)
                    mma_16816(acc[mt][nt], a[mt], b[nt]);
        }
        __syncthreads();
    }

    const int g = lane >> 2;
    const int q = lane & 3;
    if (Ch != nullptr) {
#pragma unroll
        for (int mt = 0; mt < 2; mt++) {
#pragma unroll
            for (int nt = 0; nt < 8; nt++) {
                int row = bm + m_off + mt * 16 + g;
                int col = bn + n_off + nt * 8 + q * 2;
                uint32_t h0 = pack_bf(acc[mt][nt][0], acc[mt][nt][1]);
                uint32_t l0 = pack_bf(acc[mt][nt][0] - bf_lo(h0),
                                      acc[mt][nt][1] - bf_hi(h0));
                *(uint32_t*)(Ch + (size_t)row * D_MODEL + col) = h0;
                *(uint32_t*)(Cl + (size_t)row * D_MODEL + col) = l0;
                uint32_t h1 = pack_bf(acc[mt][nt][2], acc[mt][nt][3]);
                uint32_t l1 = pack_bf(acc[mt][nt][2] - bf_lo(h1),
                                      acc[mt][nt][3] - bf_hi(h1));
                *(uint32_t*)(Ch + (size_t)(row + 8) * D_MODEL + col) = h1;
                *(uint32_t*)(Cl + (size_t)(row + 8) * D_MODEL + col) = l1;
            }
        }
    } else {
#pragma unroll
        for (int mt = 0; mt < 2; mt++) {
#pragma unroll
            for (int nt = 0; nt < 8; nt++) {
                int row = bm + m_off + mt * 16 + g;
                int col = bn + n_off + nt * 8 + q * 2;
                *(float2*)(Cf + (size_t)row * D_MODEL + col) =
                    make_float2(acc[mt][nt][0], acc[mt][nt][1]);
                *(float2*)(Cf + (size_t)(row + 8) * D_MODEL + col) =
                    make_float2(acc[mt][nt][2], acc[mt][nt][3]);
            }
        }
    }
}

// ---------------------------------------------------------------------------
// Tensor-core causal flash attention (FA2-style register softmax).
// CTA: 128 q-rows x one head, 4 warps (32 rows each). 64-key tiles,
// double-buffered cp.async of K/V hi+lo. Scores: 3-term bf16 split QK^T.
// PV: 3-term split (Phi*Vhi + Phi*Vlo + Plo*Vhi). Output -> bf16 hi/lo.
// Smem rows padded to 144B -> conflict-free ldmatrix. V via ldmatrix.trans.
// ---------------------------------------------------------------------------
#define AQT 128
#define AKT 64
#define AROWB 144
#define AQ_BYTES   (128 * AROWB)       // 18432
#define AKV_BYTES  (64 * AROWB)        // 9216
#define ASET_BYTES (4 * AKV_BYTES)     // 36864
#define ASM_KV0    (2 * AQ_BYTES)      // 36864
#define ASM_TOTAL  (ASM_KV0 + 2 * ASET_BYTES)   // 110592

__device__ __forceinline__ void load_kv_tile(
    const __nv_bfloat16* __restrict__ Kh, const __nv_bfloat16* __restrict__ Kl,
    const __nv_bfloat16* __restrict__ Vh, const __nv_bfloat16* __restrict__ Vl,
    int k0, int h, uint32_t base, int tid)
{
#pragma unroll
    for (int t = 0; t < 16; t++) {
        const __nv_bfloat16* src = (t < 4) ? Kh : (t < 8) ? Kl : (t < 12) ? Vh : Vl;
        int v = (t & 3) * 128 + tid;        // 0..511
        int r = v >> 3, c = v & 7;
        cp_async16(base + (t >> 2) * AKV_BYTES + r * AROWB + c * 16,
                   src + (size_t)(k0 + r) * D_MODEL + h * D_K + c * 8);
    }
    asm volatile("cp.async.commit_group;\n" ::: "memory");
}

__global__ __launch_bounds__(128) void flash_mma_kernel(
    const __nv_bfloat16* __restrict__ Qh, const __nv_bfloat16* __restrict__ Ql,
    const __nv_bfloat16* __restrict__ Kh, const __nv_bfloat16* __restrict__ Kl,
    const __nv_bfloat16* __restrict__ Vh, const __nv_bfloat16* __restrict__ Vl,
    __nv_bfloat16* __restrict__ Ch, __nv_bfloat16* __restrict__ Cl)
{
    extern __shared__ char smem[];
    const uint32_t sb = smem_u32(smem);
    const int tid  = threadIdx.x;
    const int lane = tid & 31;
    const int wid  = tid >> 5;
    const int m_off = wid * 32;
    const int h  = blockIdx.y;
    const int q0 = (int)(gridDim.x - 1 - blockIdx.x) * AQT;   // heavy blocks first
    const int g  = lane >> 2;
    const int qd = lane & 3;

    // Stage Q (hi at +0, lo at +AQ_BYTES); 16 chunks of 16B per thread
#pragma unroll
    for (int t = 0; t < 16; t++) {
        const __nv_bfloat16* src = (t < 8) ? Qh : Ql;
        int v = (t & 7) * 128 + tid;        // 0..1023
        int r = v >> 3, c = v & 7;
        cp_async16(sb + (t >> 3) * AQ_BYTES + r * AROWB + c * 16,
                   src + (size_t)(q0 + r) * D_MODEL + h * D_K + c * 8);
    }
    asm volatile("cp.async.commit_group;\n" ::: "memory");

    const int ntiles = q0 / AKT + 2;
    load_kv_tile(Kh, Kl, Vh, Vl, 0, h, sb + ASM_KV0, tid);

    float m_i[2][2], l_i[2][2];
    float O[2][8][4];
#pragma unroll
    for (int mt = 0; mt < 2; mt++) {
        m_i[mt][0] = -1e30f; m_i[mt][1] = -1e30f;
        l_i[mt][0] = 0.f;    l_i[mt][1] = 0.f;
#pragma unroll
        for (int no = 0; no < 8; no++)
#pragma unroll
            for (int i = 0; i < 4; i++) O[mt][no][i] = 0.f;
    }

    const float C1 = 0.18033688011112042f;   // log2(e) / sqrt(64)

    for (int t = 0; t < ntiles; t++) {
        const uint32_t kvb = sb + ASM_KV0 + (uint32_t)(t & 1) * ASET_BYTES;
        if (t + 1 < ntiles) {
            load_kv_tile(Kh, Kl, Vh, Vl, (t + 1) * AKT, h,
                         sb + ASM_KV0 + (uint32_t)((t + 1) & 1) * ASET_BYTES, tid);
            asm volatile("cp.async.wait_group 1;\n" ::: "memory");
        } else {
            asm volatile("cp.async.wait_group 0;\n" ::: "memory");
        }
        __syncthreads();

        const int k0 = t * AKT;
        const bool domask = (k0 + AKT > q0);

#pragma unroll
        for (int mt = 0; mt < 2; mt++) {
            // ---- scores: S[128-row-slice 32 x 64 keys], 3-term split ----
            float S[8][4];
#pragma unroll
            for (int nt = 0; nt < 8; nt++)
#pragma unroll
                for (int i = 0; i < 4; i++) S[nt][i] = 0.f;

#pragma unroll
            for (int ks = 0; ks < 4; ks++) {
                uint32_t qa[4], qla[4];
                uint32_t qaddr = sb + (uint32_t)(m_off + mt * 16 + (lane & 15)) * AROWB
                               + 16 * (lane >> 4) + ks * 32;
                ldsm_x4(qa, qaddr);
                ldsm_x4(qla, qaddr + AQ_BYTES);

                uint32_t bh[8][2], bl[8][2];
#pragma unroll
                for (int np = 0; np < 4; np++) {
                    uint32_t boff = (uint32_t)((lane & 7) + 8 * (lane >> 4) + np * 16) * AROWB
                                  + 16 * ((lane >> 3) & 1) + ks * 32;
                    uint32_t r4[4];
                    ldsm_x4(r4, kvb + boff);                 // Kh
                    bh[2*np][0] = r4[0]; bh[2*np][1] = r4[1];
                    bh[2*np+1][0] = r4[2]; bh[2*np+1][1] = r4[3];
                    ldsm_x4(r4, kvb + AKV_BYTES + boff);     // Kl
                    bl[2*np][0] = r4[0]; bl[2*np][1] = r4[1];
                    bl[2*np+1][0] = r4[2]; bl[2*np+1][1] = r4[3];
                }
#pragma unroll
                for (int nt = 0; nt < 8; nt++) {
                    mma_16816(S[nt], qa,  bh[nt]);
                    mma_16816(S[nt], qa,  bl[nt]);
                    mma_16816(S[nt], qla, bh[nt]);
                }
            }

            // ---- causal mask (only the last two tiles of each block) ----
            if (domask) {
                int qg0 = q0 + m_off + mt * 16 + g;
#pragma unroll
                for (int nt = 0; nt < 8; nt++) {
                    int kg = k0 + nt * 8 + 2 * qd;
                    if (kg     > qg0)     S[nt][0] = -1e30f;
                    if (kg + 1 > qg0)     S[nt][1] = -1e30f;
                    if (kg     > qg0 + 8) S[nt][2] = -1e30f;
                    if (kg + 1 > qg0 + 8) S[nt][3] = -1e30f;
                }
            }

            // ---- online softmax per row half (rows g and g+8) ----
#pragma unroll
            for (int hf = 0; hf < 2; hf++) {
                float mx = -1e30f;
#pragma unroll
                for (int nt = 0; nt < 8; nt++)
                    mx = fmaxf(mx, fmaxf(S[nt][2*hf], S[nt][2*hf+1]));
                mx = fmaxf(mx, __shfl_xor_sync(0xffffffffu, mx, 1));
                mx = fmaxf(mx, __shfl_xor_sync(0xffffffffu, mx, 2));
                float mold = m_i[mt][hf];
                float mnew = fmaxf(mold, mx);
                float f  = fast_exp2((mold - mnew) * C1);
                float nm = mnew * C1;
                float sum = 0.f;
#pragma unroll
                for (int nt = 0; nt < 8; nt++) {
                    float p0 = fast_exp2(fmaf(S[nt][2*hf],   C1, -nm));
                    float p1 = fast_exp2(fmaf(S[nt][2*hf+1], C1, -nm));
                    S[nt][2*hf] = p0; S[nt][2*hf+1] = p1;
                    sum += p0 + p1;
                }
                sum += __shfl_xor_sync(0xffffffffu, sum, 1);
                sum += __shfl_xor_sync(0xffffffffu, sum, 2);
                l_i[mt][hf] = l_i[mt][hf] * f + sum;
                m_i[mt][hf] = mnew;
#pragma unroll
                for (int no = 0; no < 8; no++) {
                    O[mt][no][2*hf]   *= f;
                    O[mt][no][2*hf+1] *= f;
                }
            }

            // ---- P·V: 3-term split; P fragments re-packed from S regs ----
#pragma unroll
            for (int j = 0; j < 4; j++) {
                uint32_t ah[4], al[4];
                ah[0] = pack_bf(S[2*j][0],   S[2*j][1]);
                ah[1] = pack_bf(S[2*j][2],   S[2*j][3]);
                ah[2] = pack_bf(S[2*j+1][0], S[2*j+1][1]);
                ah[3] = pack_bf(S[2*j+1][2], S[2*j+1][3]);
                al[0] = pack_bf(S[2*j][0]   - bf_lo(ah[0]), S[2*j][1]   - bf_hi(ah[0]));
                al[1] = pack_bf(S[2*j][2]   - bf_lo(ah[1]), S[2*j][3]   - bf_hi(ah[1]));
                al[2] = pack_bf(S[2*j+1][0] - bf_lo(ah[2]), S[2*j+1][1] - bf_hi(ah[2]));
                al[3] = pack_bf(S[2*j+1][2] - bf_lo(ah[3]), S[2*j+1][3] - bf_hi(ah[3]));

                uint32_t bvh[8][2], bvl[8][2];
#pragma unroll
                for (int np = 0; np < 4; np++) {
                    uint32_t voff = (uint32_t)(j * 16 + (lane & 7) + 8 * ((lane >> 3) & 1)) * AROWB
                                  + 16 * (lane >> 4) + np * 32;
                    uint32_t r4[4];
                    ldsm_x4_t(r4, kvb + 2 * AKV_BYTES + voff);   // Vh
                    bvh[2*np][0] = r4[0]; bvh[2*np][1] = r4[1];
                    bvh[2*np+1][0] = r4[2]; bvh[2*np+1][1] = r4[3];
                    ldsm_x4_t(r4, kvb + 3 * AKV_BYTES + voff);   // Vl
                    bvl[2*np][0] = r4[0]; bvl[2*np][1] = r4[1];
                    bvl[2*np+1][0] = r4[2]; bvl[2*np+1][1] = r4[3];
                }
#pragma unroll
                for (int no = 0; no < 8; no++) {
                    mma_16816(O[mt][no], ah, bvh[no]);
                    mma_16816(O[mt][no], ah, bvl[no]);
                    mma_16816(O[mt][no], al, bvh[no]);
                }
            }
        }
        __syncthreads();
    }

    // ---- epilogue: normalize + write bf16 hi/lo context ----
#pragma unroll
    for (int mt = 0; mt < 2; mt++) {
        float inv0 = 1.f / l_i[mt][0];
        float inv1 = 1.f / l_i[mt][1];
        int r0 = q0 + m_off + mt * 16 + g;
#pragma unroll
        for (int no = 0; no < 8; no++) {
            int col = h * D_K + no * 8 + 2 * qd;
            float o0 = O[mt][no][0] * inv0, o1 = O[mt][no][1] * inv0;
            float o2 = O[mt][no][2] * inv1, o3 = O[mt][no][3] * inv1;
            uint32_t h0 = pack_bf(o0, o1);
            uint32_t l0 = pack_bf(o0 - bf_lo(h0), o1 - bf_hi(h0));
            *(uint32_t*)(Ch + (size_t)r0 * D_MODEL + col) = h0;
            *(uint32_t*)(Cl + (size_t)r0 * D_MODEL + col) = l0;
            uint32_t h1 = pack_bf(o2, o3);
            uint32_t l1 = pack_bf(o2 - bf_lo(h1), o3 - bf_hi(h1));
            *(uint32_t*)(Ch + (size_t)(r0 + 8) * D_MODEL + col) = h1;
            *(uint32_t*)(Cl + (size_t)(r0 + 8) * D_MODEL + col) = l1;
        }
    }
}

// ---------------------------------------------------------------------------
// Launch
// ---------------------------------------------------------------------------
extern "C" void kernel_launch(void* const* d_in, const int* in_sizes, int n_in,
                              void* d_out, int out_size)
{
    const float* x   = (const float*)d_in[0];
    const float* W_q = (const float*)d_in[1];
    const float* W_k = (const float*)d_in[2];
    const float* W_v = (const float*)d_in[3];
    const float* W_o = (const float*)d_in[4];
    float* out = (float*)d_out;

    static __nv_bfloat16* xh = nullptr;
    static __nv_bfloat16 *xl, *ch, *cl, *qh, *ql, *kh, *kl, *vh, *vl;
    static __nv_bfloat16 *wqh, *wql, *wkh, *wkl, *wvh, *wvl, *woh, *wol;
    if (xh == nullptr) {
        cudaGetSymbolAddress((void**)&xl, g_xl);
        cudaGetSymbolAddress((void**)&ch, g_ch);
        cudaGetSymbolAddress((void**)&cl, g_cl);
        cudaGetSymbolAddress((void**)&qh, g_Qh);
        cudaGetSymbolAddress((void**)&ql, g_Ql);
        cudaGetSymbolAddress((void**)&kh, g_Kh);
        cudaGetSymbolAddress((void**)&kl, g_Kl);
        cudaGetSymbolAddress((void**)&vh, g_Vh);
        cudaGetSymbolAddress((void**)&vl, g_Vl);
        cudaGetSymbolAddress((void**)&wqh, g_wqh);
        cudaGetSymbolAddress((void**)&wql, g_wql);
        cudaGetSymbolAddress((void**)&wkh, g_wkh);
        cudaGetSymbolAddress((void**)&wkl, g_wkl);
        cudaGetSymbolAddress((void**)&wvh, g_wvh);
        cudaGetSymbolAddress((void**)&wvl, g_wvl);
        cudaGetSymbolAddress((void**)&woh, g_woh);
        cudaGetSymbolAddress((void**)&wol, g_wol);
        cudaFuncSetAttribute(flash_mma_kernel,
                             cudaFuncAttributeMaxDynamicSharedMemorySize, ASM_TOTAL);
        cudaGetSymbolAddress((void**)&xh, g_xh);   // last: publishes init
    }

    const int n_x4 = S_LEN * D_MODEL / 4;
    const int n_w4 = D_MODEL * D_MODEL / 4;
    split_bf16_kernel<<<(n_x4 + 255) / 256, 256>>>(x, xh, xl, n_x4);
    split_bf16_kernel<<<(n_w4 + 255) / 256, 256>>>(W_q, wqh, wql, n_w4);
    split_bf16_kernel<<<(n_w4 + 255) / 256, 256>>>(W_k, wkh, wkl, n_w4);
    split_bf16_kernel<<<(n_w4 + 255) / 256, 256>>>(W_v, wvh, wvl, n_w4);
    split_bf16_kernel<<<(n_w4 + 255) / 256, 256>>>(W_o, woh, wol, n_w4);

    dim3 ggrid(D_MODEL / 128, S_LEN / 128);   // (8, 32)
    gemm_mma_kernel<<<ggrid, 256>>>(xh, xl, wqh, wql, nullptr, qh, ql);
    gemm_mma_kernel<<<ggrid, 256>>>(xh, xl, wkh, wkl, nullptr, kh, kl);
    gemm_mma_kernel<<<ggrid, 256>>>(xh, xl, wvh, wvl, nullptr, vh, vl);

    dim3 agrid(S_LEN / AQT, NHEADS);          // (32, 16)
    flash_mma_kernel<<<agrid, 128, ASM_TOTAL>>>(qh, ql, kh, kl, vh, vl, ch, cl);

    gemm_mma_kernel<<<ggrid, 256>>>(ch, cl, woh, wol, out, nullptr, nullptr);
}

// round 5
// speedup vs baseline: 3.6943x; 1.0440x over previous
#include <cuda_runtime.h>
#include <cuda_bf16.h>
#include <math.h>
#include <stdint.h>

// Problem constants (fixed shapes per reference)
#define S_LEN   4096
#define D_MODEL 1024
#define NHEADS  16
#define D_K     64

// ---------------------------------------------------------------------------
// Scratch (device globals; no allocation allowed)
// ---------------------------------------------------------------------------
__device__ __nv_bfloat16 g_xh[S_LEN * D_MODEL];
__device__ __nv_bfloat16 g_xl[S_LEN * D_MODEL];
__device__ __nv_bfloat16 g_ch[S_LEN * D_MODEL];
__device__ __nv_bfloat16 g_cl[S_LEN * D_MODEL];
__device__ __nv_bfloat16 g_Qh[S_LEN * D_MODEL];
__device__ __nv_bfloat16 g_Ql[S_LEN * D_MODEL];
__device__ __nv_bfloat16 g_Kh[S_LEN * D_MODEL];
__device__ __nv_bfloat16 g_Kl[S_LEN * D_MODEL];
__device__ __nv_bfloat16 g_Vh[S_LEN * D_MODEL];
__device__ __nv_bfloat16 g_Vl[S_LEN * D_MODEL];
__device__ __nv_bfloat16 g_wqh[D_MODEL * D_MODEL];
__device__ __nv_bfloat16 g_wql[D_MODEL * D_MODEL];
__device__ __nv_bfloat16 g_wkh[D_MODEL * D_MODEL];
__device__ __nv_bfloat16 g_wkl[D_MODEL * D_MODEL];
__device__ __nv_bfloat16 g_wvh[D_MODEL * D_MODEL];
__device__ __nv_bfloat16 g_wvl[D_MODEL * D_MODEL];
__device__ __nv_bfloat16 g_woh[D_MODEL * D_MODEL];
__device__ __nv_bfloat16 g_wol[D_MODEL * D_MODEL];

// ---------------------------------------------------------------------------
// PTX helpers (base sm_80+ features only — build targets plain compute_103)
// ---------------------------------------------------------------------------
__device__ __forceinline__ uint32_t smem_u32(const void* p) {
    uint32_t a;
    asm("{ .reg .u64 t; cvta.to.shared.u64 t, %1; cvt.u32.u64 %0, t; }"
        : "=r"(a) : "l"(p));
    return a;
}

__device__ __forceinline__ void cp_async16(uint32_t smem_dst, const void* gmem_src) {
    asm volatile("cp.async.cg.shared.global [%0], [%1], 16;\n"
                 :: "r"(smem_dst), "l"(gmem_src));
}

__device__ __forceinline__ void ldsm_x4(uint32_t* r, uint32_t addr) {
    asm volatile("ldmatrix.sync.aligned.m8n8.x4.shared.b16 {%0,%1,%2,%3}, [%4];"
                 : "=r"(r[0]), "=r"(r[1]), "=r"(r[2]), "=r"(r[3]) : "r"(addr));
}

__device__ __forceinline__ void ldsm_x4_t(uint32_t* r, uint32_t addr) {
    asm volatile("ldmatrix.sync.aligned.m8n8.x4.trans.shared.b16 {%0,%1,%2,%3}, [%4];"
                 : "=r"(r[0]), "=r"(r[1]), "=r"(r[2]), "=r"(r[3]) : "r"(addr));
}

__device__ __forceinline__ void mma_16816(float* d, const uint32_t* a, const uint32_t* b) {
    asm volatile(
        "mma.sync.aligned.m16n8k16.row.col.f32.bf16.bf16.f32 "
        "{%0,%1,%2,%3}, {%4,%5,%6,%7}, {%8,%9}, {%0,%1,%2,%3};"
        : "+f"(d[0]), "+f"(d[1]), "+f"(d[2]), "+f"(d[3])
        : "r"(a[0]), "r"(a[1]), "r"(a[2]), "r"(a[3]), "r"(b[0]), "r"(b[1]));
}

__device__ __forceinline__ float fast_exp2(float x) {
    float r; asm("ex2.approx.f32 %0, %1;" : "=f"(r) : "f"(x)); return r;
}

// pack two fp32 -> bf16x2 (x in low half, y in high half)
__device__ __forceinline__ uint32_t pack_bf(float x, float y) {
    uint32_t r;
    asm("cvt.rn.bf16x2.f32 %0, %1, %2;" : "=r"(r) : "f"(y), "f"(x));
    return r;
}
__device__ __forceinline__ float bf_lo(uint32_t r) { return __uint_as_float(r << 16); }
__device__ __forceinline__ float bf_hi(uint32_t r) { return __uint_as_float(r & 0xffff0000u); }

// ---------------------------------------------------------------------------
// Split fp32 -> bf16 hi/lo  (hi = bf16(x), lo = bf16(x - float(hi)))
// ---------------------------------------------------------------------------
__global__ void split_bf16_kernel(const float* __restrict__ in,
                                  __nv_bfloat16* __restrict__ hi,
                                  __nv_bfloat16* __restrict__ lo, int n4)
{
    int i = blockIdx.x * blockDim.x + threadIdx.x;
    if (i >= n4) return;
    float4 v = ((const float4*)in)[i];
    uint32_t h01 = pack_bf(v.x, v.y);
    uint32_t h23 = pack_bf(v.z, v.w);
    uint32_t l01 = pack_bf(v.x - bf_lo(h01), v.y - bf_hi(h01));
    uint32_t l23 = pack_bf(v.z - bf_lo(h23), v.w - bf_hi(h23));
    ((uint32_t*)hi)[i * 2 + 0] = h01;
    ((uint32_t*)hi)[i * 2 + 1] = h23;
    ((uint32_t*)lo)[i * 2 + 0] = l01;
    ((uint32_t*)lo)[i * 2 + 1] = l23;
}

// ---------------------------------------------------------------------------
// Tensor-core GEMM via mma.sync (HMMA, bf16, fp32 acc):
//   C[4096,1024] = Ahi*Bhi^T + Ahi*Blo^T + Alo*Bhi^T
// One pass over 32 K-chunks; each stage holds Ah/Al/Bh/Bl tiles (BK=32),
// 2-stage cp.async. 3 split terms issued per chunk (loads each tile once).
// Epilogue: if Ch != null, write bf16 hi/lo pair; else fp32 Cf.
// ---------------------------------------------------------------------------
#define GK     1024
#define GBK    32
#define ROWB   80
#define TILEB  (128 * ROWB)     // 10240
#define SETB   (4 * TILEB)      // 40960 per stage
#define GSM_TOTAL (2 * SETB)    // 81920
#define NKCH   32

__device__ __forceinline__ void load_chunk4(
    const __nv_bfloat16* __restrict__ Ah, const __nv_bfloat16* __restrict__ Al,
    const __nv_bfloat16* __restrict__ Bh, const __nv_bfloat16* __restrict__ Bl,
    int bm, int bn, int k0, uint32_t dst, int tid)
{
#pragma unroll
    for (int t = 0; t < 2; t++) {
        int u = tid + t * 256;
        int r = u >> 2;
        int c = (u & 3) * 16;
        size_t ao = (size_t)(bm + r) * GK + k0;
        size_t bo = (size_t)(bn + r) * GK + k0;
        uint32_t so = (uint32_t)(r * ROWB + c);
        cp_async16(dst + so,             (const char*)(Ah + ao) + c);
        cp_async16(dst + TILEB + so,     (const char*)(Al + ao) + c);
        cp_async16(dst + 2 * TILEB + so, (const char*)(Bh + bo) + c);
        cp_async16(dst + 3 * TILEB + so, (const char*)(Bl + bo) + c);
    }
    asm volatile("cp.async.commit_group;\n" ::: "memory");
}

__global__ __launch_bounds__(256, 2) void gemm_mma_kernel(
    const __nv_bfloat16* __restrict__ A_hi, const __nv_bfloat16* __restrict__ A_lo,
    const __nv_bfloat16* __restrict__ B_hi, const __nv_bfloat16* __restrict__ B_lo,
    float* __restrict__ Cf,
    __nv_bfloat16* __restrict__ Ch, __nv_bfloat16* __restrict__ Cl)
{
    extern __shared__ __align__(16) char gsm[];
    const uint32_t sb = smem_u32(gsm);

    const int tid  = threadIdx.x;
    const int lane = tid & 31;
    const int w    = tid >> 5;
    const int m_off = (w & 3) * 32;
    const int n_off = (w >> 2) * 64;
    const int bm = blockIdx.y * 128;
    const int bn = blockIdx.x * 128;

    float acc[2][8][4];
#pragma unroll
    for (int mt = 0; mt < 2; mt++)
#pragma unroll
        for (int nt = 0; nt < 8; nt++)
#pragma unroll
            for (int i = 0; i < 4; i++) acc[mt][nt][i] = 0.0f;

    const uint32_t a_off = (uint32_t)((m_off + (lane & 15)) * ROWB + 16 * (lane >> 4));
    const uint32_t b_off = (uint32_t)((n_off + (lane & 7) + 8 * (lane >> 4)) * ROWB
                                      + 16 * ((lane >> 3) & 1));

    load_chunk4(A_hi, A_lo, B_hi, B_lo, bm, bn, 0,   sb,        tid);
    load_chunk4(A_hi, A_lo, B_hi, B_lo, bm, bn, GBK, sb + SETB, tid);

    for (int i = 0; i < NKCH; i++) {
        if (i + 1 < NKCH) {
            asm volatile("cp.async.wait_group 1;\n" ::: "memory");
        } else {
            asm volatile("cp.async.wait_group 0;\n" ::: "memory");
        }
        __syncthreads();

        const uint32_t base = sb + (uint32_t)(i & 1) * SETB;
#pragma unroll
        for (int ks = 0; ks < 2; ks++) {
            uint32_t ah[2][4], al[2][4];
#pragma unroll
            for (int mt = 0; mt < 2; mt++) {
                uint32_t aadr = base + a_off + (uint32_t)(mt * 16 * ROWB + ks * 32);
                ldsm_x4(ah[mt], aadr);
                ldsm_x4(al[mt], aadr + TILEB);
            }
            uint32_t b2[8][2];
            // Bh: terms ah*bh and al*bh
#pragma unroll
            for (int np = 0; np < 4; np++) {
                uint32_t r4[4];
                ldsm_x4(r4, base + 2 * TILEB + b_off + (uint32_t)(np * 16 * ROWB + ks * 32));
                b2[2*np][0] = r4[0]; b2[2*np][1] = r4[1];
                b2[2*np+1][0] = r4[2]; b2[2*np+1][1] = r4[3];
            }
#pragma unroll
            for (int mt = 0; mt < 2; mt++)
#pragma unroll
                for (int nt = 0; nt < 8; nt++) {
                    mma_16816(acc[mt][nt], ah[mt], b2[nt]);
                    mma_16816(acc[mt][nt], al[mt], b2[nt]);
                }
            // Bl: term ah*bl
#pragma unroll
            for (int np = 0; np < 4; np++) {
                uint32_t r4[4];
                ldsm_x4(r4, base + 3 * TILEB + b_off + (uint32_t)(np * 16 * ROWB + ks * 32));
                b2[2*np][0] = r4[0]; b2[2*np][1] = r4[1];
                b2[2*np+1][0] = r4[2]; b2[2*np+1][1] = r4[3];
            }
#pragma unroll
            for (int mt = 0; mt < 2; mt++)
#pragma unroll
                for (int nt = 0; nt < 8; nt++)
                    mma_16816(acc[mt][nt], ah[mt], b2[nt]);
        }
        __syncthreads();

        if (i + 2 < NKCH)
            load_chunk4(A_hi, A_lo, B_hi, B_lo, bm, bn, (i + 2) * GBK, base, tid);
    }

    const int g = lane >> 2;
    const int q = lane & 3;
    if (Ch != nullptr) {
#pragma unroll
        for (int mt = 0; mt < 2; mt++) {
#pragma unroll
            for (int nt = 0; nt < 8; nt++) {
                int row = bm + m_off + mt * 16 + g;
                int col = bn + n_off + nt * 8 + q * 2;
                uint32_t h0 = pack_bf(acc[mt][nt][0], acc[mt][nt][1]);
                uint32_t l0 = pack_bf(acc[mt][nt][0] - bf_lo(h0),
                                      acc[mt][nt][1] - bf_hi(h0));
                *(uint32_t*)(Ch + (size_t)row * D_MODEL + col) = h0;
                *(uint32_t*)(Cl + (size_t)row * D_MODEL + col) = l0;
                uint32_t h1 = pack_bf(acc[mt][nt][2], acc[mt][nt][3]);
                uint32_t l1 = pack_bf(acc[mt][nt][2] - bf_lo(h1),
                                      acc[mt][nt][3] - bf_hi(h1));
                *(uint32_t*)(Ch + (size_t)(row + 8) * D_MODEL + col) = h1;
                *(uint32_t*)(Cl + (size_t)(row + 8) * D_MODEL + col) = l1;
            }
        }
    } else {
#pragma unroll
        for (int mt = 0; mt < 2; mt++) {
#pragma unroll
            for (int nt = 0; nt < 8; nt++) {
                int row = bm + m_off + mt * 16 + g;
                int col = bn + n_off + nt * 8 + q * 2;
                *(float2*)(Cf + (size_t)row * D_MODEL + col) =
                    make_float2(acc[mt][nt][0], acc[mt][nt][1]);
                *(float2*)(Cf + (size_t)(row + 8) * D_MODEL + col) =
                    make_float2(acc[mt][nt][2], acc[mt][nt][3]);
            }
        }
    }
}

// ---------------------------------------------------------------------------
// Tensor-core causal flash attention (FA2-style register softmax).
// CTA: 128 q-rows x one head, 4 warps. 64-key tiles, double-buffered
// cp.async K/V hi+lo. K/V fragments loaded ONCE per ks/j and shared across
// both 16-row sub-tiles (mt). 3-term bf16 splits on scores and PV.
// ---------------------------------------------------------------------------
#define AQT 128
#define AKT 64
#define AROWB 144
#define AQ_BYTES   (128 * AROWB)       // 18432
#define AKV_BYTES  (64 * AROWB)        // 9216
#define ASET_BYTES (4 * AKV_BYTES)     // 36864
#define ASM_KV0    (2 * AQ_BYTES)      // 36864
#define ASM_TOTAL  (ASM_KV0 + 2 * ASET_BYTES)   // 110592

__device__ __forceinline__ void load_kv_tile(
    const __nv_bfloat16* __restrict__ Kh, const __nv_bfloat16* __restrict__ Kl,
    const __nv_bfloat16* __restrict__ Vh, const __nv_bfloat16* __restrict__ Vl,
    int k0, int h, uint32_t base, int tid)
{
#pragma unroll
    for (int t = 0; t < 16; t++) {
        const __nv_bfloat16* src = (t < 4) ? Kh : (t < 8) ? Kl : (t < 12) ? Vh : Vl;
        int v = (t & 3) * 128 + tid;        // 0..511
        int r = v >> 3, c = v & 7;
        cp_async16(base + (t >> 2) * AKV_BYTES + r * AROWB + c * 16,
                   src + (size_t)(k0 + r) * D_MODEL + h * D_K + c * 8);
    }
    asm volatile("cp.async.commit_group;\n" ::: "memory");
}

__global__ __launch_bounds__(128) void flash_mma_kernel(
    const __nv_bfloat16* __restrict__ Qh, const __nv_bfloat16* __restrict__ Ql,
    const __nv_bfloat16* __restrict__ Kh, const __nv_bfloat16* __restrict__ Kl,
    const __nv_bfloat16* __restrict__ Vh, const __nv_bfloat16* __restrict__ Vl,
    __nv_bfloat16* __restrict__ Ch, __nv_bfloat16* __restrict__ Cl)
{
    extern __shared__ char smem[];
    const uint32_t sb = smem_u32(smem);
    const int tid  = threadIdx.x;
    const int lane = tid & 31;
    const int wid  = tid >> 5;
    const int m_off = wid * 32;
    const int h  = blockIdx.y;
    const int q0 = (int)(gridDim.x - 1 - blockIdx.x) * AQT;   // heavy blocks first
    const int g  = lane >> 2;
    const int qd = lane & 3;

    // Stage Q (hi at +0, lo at +AQ_BYTES)
#pragma unroll
    for (int t = 0; t < 16; t++) {
        const __nv_bfloat16* src = (t < 8) ? Qh : Ql;
        int v = (t & 7) * 128 + tid;
        int r = v >> 3, c = v & 7;
        cp_async16(sb + (t >> 3) * AQ_BYTES + r * AROWB + c * 16,
                   src + (size_t)(q0 + r) * D_MODEL + h * D_K + c * 8);
    }
    asm volatile("cp.async.commit_group;\n" ::: "memory");

    const int ntiles = q0 / AKT + 2;
    load_kv_tile(Kh, Kl, Vh, Vl, 0, h, sb + ASM_KV0, tid);

    float m_i[2][2], l_i[2][2];
    float O[2][8][4];
#pragma unroll
    for (int mt = 0; mt < 2; mt++) {
        m_i[mt][0] = -1e30f; m_i[mt][1] = -1e30f;
        l_i[mt][0] = 0.f;    l_i[mt][1] = 0.f;
#pragma unroll
        for (int no = 0; no < 8; no++)
#pragma unroll
            for (int i = 0; i < 4; i++) O[mt][no][i] = 0.f;
    }

    const float C1 = 0.18033688011112042f;   // log2(e) / sqrt(64)

    // per-thread fragment offsets (tile-invariant)
    const uint32_t q_base = sb + (uint32_t)((m_off + (lane & 15)) * AROWB + 16 * (lane >> 4));
    const uint32_t k_base = (uint32_t)(((lane & 7) + 8 * (lane >> 4)) * AROWB
                                       + 16 * ((lane >> 3) & 1));
    const uint32_t v_base = (uint32_t)(((lane & 7) + 8 * ((lane >> 3) & 1)) * AROWB
                                       + 16 * (lane >> 4));

    for (int t = 0; t < ntiles; t++) {
        const uint32_t kvb = sb + ASM_KV0 + (uint32_t)(t & 1) * ASET_BYTES;
        if (t + 1 < ntiles) {
            load_kv_tile(Kh, Kl, Vh, Vl, (t + 1) * AKT, h,
                         sb + ASM_KV0 + (uint32_t)((t + 1) & 1) * ASET_BYTES, tid);
            asm volatile("cp.async.wait_group 1;\n" ::: "memory");
        } else {
            asm volatile("cp.async.wait_group 0;\n" ::: "memory");
        }
        __syncthreads();

        const int k0 = t * AKT;
        const bool domask = (k0 + AKT > q0);

        // ---- scores for BOTH mt sub-tiles; K frags loaded once per ks ----
        float S[2][8][4];
#pragma unroll
        for (int mt = 0; mt < 2; mt++)
#pragma unroll
            for (int nt = 0; nt < 8; nt++)
#pragma unroll
                for (int i = 0; i < 4; i++) S[mt][nt][i] = 0.f;

#pragma unroll
        for (int ks = 0; ks < 4; ks++) {
            uint32_t qa[2][4], qla[2][4];
#pragma unroll
            for (int mt = 0; mt < 2; mt++) {
                uint32_t qaddr = q_base + (uint32_t)(mt * 16 * AROWB + ks * 32);
                ldsm_x4(qa[mt], qaddr);
                ldsm_x4(qla[mt], qaddr + AQ_BYTES);
            }
            uint32_t b2[8][2];
            // Kh: qa*bh + qla*bh
#pragma unroll
            for (int np = 0; np < 4; np++) {
                uint32_t r4[4];
                ldsm_x4(r4, kvb + k_base + (uint32_t)(np * 16 * AROWB + ks * 32));
                b2[2*np][0] = r4[0]; b2[2*np][1] = r4[1];
                b2[2*np+1][0] = r4[2]; b2[2*np+1][1] = r4[3];
            }
#pragma unroll
            for (int mt = 0; mt < 2; mt++)
#pragma unroll
                for (int nt = 0; nt < 8; nt++) {
                    mma_16816(S[mt][nt], qa[mt], b2[nt]);
                    mma_16816(S[mt][nt], qla[mt], b2[nt]);
                }
            // Kl: qa*bl
#pragma unroll
            for (int np = 0; np < 4; np++) {
                uint32_t r4[4];
                ldsm_x4(r4, kvb + AKV_BYTES + k_base + (uint32_t)(np * 16 * AROWB + ks * 32));
                b2[2*np][0] = r4[0]; b2[2*np][1] = r4[1];
                b2[2*np+1][0] = r4[2]; b2[2*np+1][1] = r4[3];
            }
#pragma unroll
            for (int mt = 0; mt < 2; mt++)
#pragma unroll
                for (int nt = 0; nt < 8; nt++)
                    mma_16816(S[mt][nt], qa[mt], b2[nt]);
        }

        // ---- mask + online softmax per mt ----
#pragma unroll
        for (int mt = 0; mt < 2; mt++) {
            if (domask) {
                int qg0 = q0 + m_off + mt * 16 + g;
#pragma unroll
                for (int nt = 0; nt < 8; nt++) {
                    int kg = k0 + nt * 8 + 2 * qd;
                    if (kg     > qg0)     S[mt][nt][0] = -1e30f;
                    if (kg + 1 > qg0)     S[mt][nt][1] = -1e30f;
                    if (kg     > qg0 + 8) S[mt][nt][2] = -1e30f;
                    if (kg + 1 > qg0 + 8) S[mt][nt][3] = -1e30f;
                }
            }
#pragma unroll
            for (int hf = 0; hf < 2; hf++) {
                float mx = -1e30f;
#pragma unroll
                for (int nt = 0; nt < 8; nt++)
                    mx = fmaxf(mx, fmaxf(S[mt][nt][2*hf], S[mt][nt][2*hf+1]));
                mx = fmaxf(mx, __shfl_xor_sync(0xffffffffu, mx, 1));
                mx = fmaxf(mx, __shfl_xor_sync(0xffffffffu, mx, 2));
                float mold = m_i[mt][hf];
                float mnew = fmaxf(mold, mx);
                float f  = fast_exp2((mold - mnew) * C1);
                float nm = mnew * C1;
                float sum = 0.f;
#pragma unroll
                for (int nt = 0; nt < 8; nt++) {
                    float p0 = fast_exp2(fmaf(S[mt][nt][2*hf],   C1, -nm));
                    float p1 = fast_exp2(fmaf(S[mt][nt][2*hf+1], C1, -nm));
                    S[mt][nt][2*hf] = p0; S[mt][nt][2*hf+1] = p1;
                    sum += p0 + p1;
                }
                sum += __shfl_xor_sync(0xffffffffu, sum, 1);
                sum += __shfl_xor_sync(0xffffffffu, sum, 2);
                l_i[mt][hf] = l_i[mt][hf] * f + sum;
                m_i[mt][hf] = mnew;
#pragma unroll
                for (int no = 0; no < 8; no++) {
                    O[mt][no][2*hf]   *= f;
                    O[mt][no][2*hf+1] *= f;
                }
            }
        }

        // ---- P·V; V frags loaded once per j, shared across mt ----
#pragma unroll
        for (int j = 0; j < 4; j++) {
            uint32_t ph[2][4], pl[2][4];
#pragma unroll
            for (int mt = 0; mt < 2; mt++) {
                ph[mt][0] = pack_bf(S[mt][2*j][0],   S[mt][2*j][1]);
                ph[mt][1] = pack_bf(S[mt][2*j][2],   S[mt][2*j][3]);
                ph[mt][2] = pack_bf(S[mt][2*j+1][0], S[mt][2*j+1][1]);
                ph[mt][3] = pack_bf(S[mt][2*j+1][2], S[mt][2*j+1][3]);
                pl[mt][0] = pack_bf(S[mt][2*j][0]   - bf_lo(ph[mt][0]),
                                    S[mt][2*j][1]   - bf_hi(ph[mt][0]));
                pl[mt][1] = pack_bf(S[mt][2*j][2]   - bf_lo(ph[mt][1]),
                                    S[mt][2*j][3]   - bf_hi(ph[mt][1]));
                pl[mt][2] = pack_bf(S[mt][2*j+1][0] - bf_lo(ph[mt][2]),
                                    S[mt][2*j+1][1] - bf_hi(ph[mt][2]));
                pl[mt][3] = pack_bf(S[mt][2*j+1][2] - bf_lo(ph[mt][3]),
                                    S[mt][2*j+1][3] - bf_hi(ph[mt][3]));
            }
            uint32_t v2[8][2];
            // Vh: ph*vh + pl*vh
#pragma unroll
            for (int np = 0; np < 4; np++) {
                uint32_t r4[4];
                ldsm_x4_t(r4, kvb + 2 * AKV_BYTES + v_base
                              + (uint32_t)(j * 16 * AROWB + np * 32));
                v2[2*np][0] = r4[0]; v2[2*np][1] = r4[1];
                v2[2*np+1][0] = r4[2]; v2[2*np+1][1] = r4[3];
            }
#pragma unroll
            for (int mt = 0; mt < 2; mt++)
#pragma unroll
                for (int no = 0; no < 8; no++) {
                    mma_16816(O[mt][no], ph[mt], v2[no]);
                    mma_16816(O[mt][no], pl[mt], v2[no]);
                }
            // Vl: ph*vl
#pragma unroll
            for (int np = 0; np < 4; np++) {
                uint32_t r4[4];
                ldsm_x4_t(r4, kvb + 3 * AKV_BYTES + v_base
                              + (uint32_t)(j * 16 * AROWB + np * 32));
                v2[2*np][0] = r4[0]; v2[2*np][1] = r4[1];
                v2[2*np+1][0] = r4[2]; v2[2*np+1][1] = r4[3];
            }
#pragma unroll
            for (int mt = 0; mt < 2; mt++)
#pragma unroll
                for (int no = 0; no < 8; no++)
                    mma_16816(O[mt][no], ph[mt], v2[no]);
        }
        __syncthreads();
    }

    // ---- epilogue: normalize + write bf16 hi/lo context ----
#pragma unroll
    for (int mt = 0; mt < 2; mt++) {
        float inv0 = 1.f / l_i[mt][0];
        float inv1 = 1.f / l_i[mt][1];
        int r0 = q0 + m_off + mt * 16 + g;
#pragma unroll
        for (int no = 0; no < 8; no++) {
            int col = h * D_K + no * 8 + 2 * qd;
            float o0 = O[mt][no][0] * inv0, o1 = O[mt][no][1] * inv0;
            float o2 = O[mt][no][2] * inv1, o3 = O[mt][no][3] * inv1;
            uint32_t h0 = pack_bf(o0, o1);
            uint32_t l0 = pack_bf(o0 - bf_lo(h0), o1 - bf_hi(h0));
            *(uint32_t*)(Ch + (size_t)r0 * D_MODEL + col) = h0;
            *(uint32_t*)(Cl + (size_t)r0 * D_MODEL + col) = l0;
            uint32_t h1 = pack_bf(o2, o3);
            uint32_t l1 = pack_bf(o2 - bf_lo(h1), o3 - bf_hi(h1));
            *(uint32_t*)(Ch + (size_t)(r0 + 8) * D_MODEL + col) = h1;
            *(uint32_t*)(Cl + (size_t)(r0 + 8) * D_MODEL + col) = l1;
        }
    }
}

// ---------------------------------------------------------------------------
// Launch
// ---------------------------------------------------------------------------
extern "C" void kernel_launch(void* const* d_in, const int* in_sizes, int n_in,
                              void* d_out, int out_size)
{
    const float* x   = (const float*)d_in[0];
    const float* W_q = (const float*)d_in[1];
    const float* W_k = (const float*)d_in[2];
    const float* W_v = (const float*)d_in[3];
    const float* W_o = (const float*)d_in[4];
    float* out = (float*)d_out;

    static __nv_bfloat16* xh = nullptr;
    static __nv_bfloat16 *xl, *ch, *cl, *qh, *ql, *kh, *kl, *vh, *vl;
    static __nv_bfloat16 *wqh, *wql, *wkh, *wkl, *wvh, *wvl, *woh, *wol;
    if (xh == nullptr) {
        cudaGetSymbolAddress((void**)&xl, g_xl);
        cudaGetSymbolAddress((void**)&ch, g_ch);
        cudaGetSymbolAddress((void**)&cl, g_cl);
        cudaGetSymbolAddress((void**)&qh, g_Qh);
        cudaGetSymbolAddress((void**)&ql, g_Ql);
        cudaGetSymbolAddress((void**)&kh, g_Kh);
        cudaGetSymbolAddress((void**)&kl, g_Kl);
        cudaGetSymbolAddress((void**)&vh, g_Vh);
        cudaGetSymbolAddress((void**)&vl, g_Vl);
        cudaGetSymbolAddress((void**)&wqh, g_wqh);
        cudaGetSymbolAddress((void**)&wql, g_wql);
        cudaGetSymbolAddress((void**)&wkh, g_wkh);
        cudaGetSymbolAddress((void**)&wkl, g_wkl);
        cudaGetSymbolAddress((void**)&wvh, g_wvh);
        cudaGetSymbolAddress((void**)&wvl, g_wvl);
        cudaGetSymbolAddress((void**)&woh, g_woh);
        cudaGetSymbolAddress((void**)&wol, g_wol);
        cudaFuncSetAttribute(flash_mma_kernel,
                             cudaFuncAttributeMaxDynamicSharedMemorySize, ASM_TOTAL);
        cudaFuncSetAttribute(gemm_mma_kernel,
                             cudaFuncAttributeMaxDynamicSharedMemorySize, GSM_TOTAL);
        cudaGetSymbolAddress((void**)&xh, g_xh);   // last: publishes init
    }

    const int n_x4 = S_LEN * D_MODEL / 4;
    const int n_w4 = D_MODEL * D_MODEL / 4;
    split_bf16_kernel<<<(n_x4 + 255) / 256, 256>>>(x, xh, xl, n_x4);
    split_bf16_kernel<<<(n_w4 + 255) / 256, 256>>>(W_q, wqh, wql, n_w4);
    split_bf16_kernel<<<(n_w4 + 255) / 256, 256>>>(W_k, wkh, wkl, n_w4);
    split_bf16_kernel<<<(n_w4 + 255) / 256, 256>>>(W_v, wvh, wvl, n_w4);
    split_bf16_kernel<<<(n_w4 + 255) / 256, 256>>>(W_o, woh, wol, n_w4);

    dim3 ggrid(D_MODEL / 128, S_LEN / 128);   // (8, 32)
    gemm_mma_kernel<<<ggrid, 256, GSM_TOTAL>>>(xh, xl, wqh, wql, nullptr, qh, ql);
    gemm_mma_kernel<<<ggrid, 256, GSM_TOTAL>>>(xh, xl, wkh, wkl, nullptr, kh, kl);
    gemm_mma_kernel<<<ggrid, 256, GSM_TOTAL>>>(xh, xl, wvh, wvl, nullptr, vh, vl);

    dim3 agrid(S_LEN / AQT, NHEADS);          // (32, 16)
    flash_mma_kernel<<<agrid, 128, ASM_TOTAL>>>(qh, ql, kh, kl, vh, vl, ch, cl);

    gemm_mma_kernel<<<ggrid, 256, GSM_TOTAL>>>(ch, cl, woh, wol, out, nullptr, nullptr);
}

// round 6
// speedup vs baseline: 3.9186x; 1.0607x over previous
#include <cuda_runtime.h>
#include <cuda_bf16.h>
#include <math.h>
#include <stdint.h>

// Problem constants (fixed shapes per reference)
#define S_LEN   4096
#define D_MODEL 1024
#define NHEADS  16
#define D_K     64

// ---------------------------------------------------------------------------
// Scratch (device globals; no allocation allowed)
// ---------------------------------------------------------------------------
__device__ __nv_bfloat16 g_xh[S_LEN * D_MODEL];
__device__ __nv_bfloat16 g_xl[S_LEN * D_MODEL];
__device__ __nv_bfloat16 g_ch[S_LEN * D_MODEL];
__device__ __nv_bfloat16 g_cl[S_LEN * D_MODEL];
__device__ __nv_bfloat16 g_Qh[S_LEN * D_MODEL];
__device__ __nv_bfloat16 g_Ql[S_LEN * D_MODEL];
__device__ __nv_bfloat16 g_Kh[S_LEN * D_MODEL];
__device__ __nv_bfloat16 g_Kl[S_LEN * D_MODEL];
__device__ __nv_bfloat16 g_Vh[S_LEN * D_MODEL];
__device__ __nv_bfloat16 g_Vl[S_LEN * D_MODEL];
__device__ __nv_bfloat16 g_wqh[D_MODEL * D_MODEL];
__device__ __nv_bfloat16 g_wql[D_MODEL * D_MODEL];
__device__ __nv_bfloat16 g_wkh[D_MODEL * D_MODEL];
__device__ __nv_bfloat16 g_wkl[D_MODEL * D_MODEL];
__device__ __nv_bfloat16 g_wvh[D_MODEL * D_MODEL];
__device__ __nv_bfloat16 g_wvl[D_MODEL * D_MODEL];
__device__ __nv_bfloat16 g_woh[D_MODEL * D_MODEL];
__device__ __nv_bfloat16 g_wol[D_MODEL * D_MODEL];

// ---------------------------------------------------------------------------
// PTX helpers (base sm_80+ features only — build targets plain compute_103)
// ---------------------------------------------------------------------------
__device__ __forceinline__ uint32_t smem_u32(const void* p) {
    uint32_t a;
    asm("{ .reg .u64 t; cvta.to.shared.u64 t, %1; cvt.u32.u64 %0, t; }"
        : "=r"(a) : "l"(p));
    return a;
}

__device__ __forceinline__ void cp_async16(uint32_t smem_dst, const void* gmem_src) {
    asm volatile("cp.async.cg.shared.global [%0], [%1], 16;\n"
                 :: "r"(smem_dst), "l"(gmem_src));
}

__device__ __forceinline__ void ldsm_x4(uint32_t* r, uint32_t addr) {
    asm volatile("ldmatrix.sync.aligned.m8n8.x4.shared.b16 {%0,%1,%2,%3}, [%4];"
                 : "=r"(r[0]), "=r"(r[1]), "=r"(r[2]), "=r"(r[3]) : "r"(addr));
}

__device__ __forceinline__ void ldsm_x4_t(uint32_t* r, uint32_t addr) {
    asm volatile("ldmatrix.sync.aligned.m8n8.x4.trans.shared.b16 {%0,%1,%2,%3}, [%4];"
                 : "=r"(r[0]), "=r"(r[1]), "=r"(r[2]), "=r"(r[3]) : "r"(addr));
}

__device__ __forceinline__ void mma_16816(float* d, const uint32_t* a, const uint32_t* b) {
    asm volatile(
        "mma.sync.aligned.m16n8k16.row.col.f32.bf16.bf16.f32 "
        "{%0,%1,%2,%3}, {%4,%5,%6,%7}, {%8,%9}, {%0,%1,%2,%3};"
        : "+f"(d[0]), "+f"(d[1]), "+f"(d[2]), "+f"(d[3])
        : "r"(a[0]), "r"(a[1]), "r"(a[2]), "r"(a[3]), "r"(b[0]), "r"(b[1]));
}

__device__ __forceinline__ float fast_exp2(float x) {
    float r; asm("ex2.approx.f32 %0, %1;" : "=f"(r) : "f"(x)); return r;
}

// pack two fp32 -> bf16x2 (x in low half, y in high half)
__device__ __forceinline__ uint32_t pack_bf(float x, float y) {
    uint32_t r;
    asm("cvt.rn.bf16x2.f32 %0, %1, %2;" : "=r"(r) : "f"(y), "f"(x));
    return r;
}
__device__ __forceinline__ float bf_lo(uint32_t r) { return __uint_as_float(r << 16); }
__device__ __forceinline__ float bf_hi(uint32_t r) { return __uint_as_float(r & 0xffff0000u); }

// ---------------------------------------------------------------------------
// Split fp32 -> bf16 hi/lo  (hi = bf16(x), lo = bf16(x - float(hi)))
// ---------------------------------------------------------------------------
__device__ __forceinline__ void split_one(const float* in, __nv_bfloat16* hi,
                                          __nv_bfloat16* lo, int i)
{
    float4 v = ((const float4*)in)[i];
    uint32_t h01 = pack_bf(v.x, v.y);
    uint32_t h23 = pack_bf(v.z, v.w);
    uint32_t l01 = pack_bf(v.x - bf_lo(h01), v.y - bf_hi(h01));
    uint32_t l23 = pack_bf(v.z - bf_lo(h23), v.w - bf_hi(h23));
    ((uint32_t*)hi)[i * 2 + 0] = h01;
    ((uint32_t*)hi)[i * 2 + 1] = h23;
    ((uint32_t*)lo)[i * 2 + 0] = l01;
    ((uint32_t*)lo)[i * 2 + 1] = l23;
}

__global__ void split_bf16_kernel(const float* __restrict__ in,
                                  __nv_bfloat16* __restrict__ hi,
                                  __nv_bfloat16* __restrict__ lo, int n4)
{
    int i = blockIdx.x * blockDim.x + threadIdx.x;
    if (i >= n4) return;
    split_one(in, hi, lo, i);
}

// All 4 weight matrices in one launch; idx>>18 routes (n_w4 = 2^18).
__global__ void split_w4_kernel(
    const float* __restrict__ w0, const float* __restrict__ w1,
    const float* __restrict__ w2, const float* __restrict__ w3,
    __nv_bfloat16* __restrict__ h0, __nv_bfloat16* __restrict__ l0,
    __nv_bfloat16* __restrict__ h1, __nv_bfloat16* __restrict__ l1,
    __nv_bfloat16* __restrict__ h2, __nv_bfloat16* __restrict__ l2,
    __nv_bfloat16* __restrict__ h3, __nv_bfloat16* __restrict__ l3)
{
    int idx = blockIdx.x * blockDim.x + threadIdx.x;
    int sel = idx >> 18;
    int i   = idx & ((1 << 18) - 1);
    const float* in = sel == 0 ? w0 : sel == 1 ? w1 : sel == 2 ? w2 : w3;
    __nv_bfloat16* hi = sel == 0 ? h0 : sel == 1 ? h1 : sel == 2 ? h2 : h3;
    __nv_bfloat16* lo = sel == 0 ? l0 : sel == 1 ? l1 : sel == 2 ? l2 : l3;
    split_one(in, hi, lo, i);
}

// ---------------------------------------------------------------------------
// Tensor-core GEMM body (HMMA, bf16, fp32 acc):
//   acc = Ahi*Bhi^T + Ahi*Blo^T + Alo*Bhi^T  over K=1024, tile 128x128
// One pass over 32 K-chunks; each stage holds Ah/Al/Bh/Bl tiles (BK=32),
// 2-stage cp.async.
// ---------------------------------------------------------------------------
#define GK     1024
#define GBK    32
#define ROWB   80
#define TILEB  (128 * ROWB)     // 10240
#define SETB   (4 * TILEB)      // 40960 per stage
#define GSM_TOTAL (2 * SETB)    // 81920
#define NKCH   32

__device__ __forceinline__ void load_chunk4(
    const __nv_bfloat16* __restrict__ Ah, const __nv_bfloat16* __restrict__ Al,
    const __nv_bfloat16* __restrict__ Bh, const __nv_bfloat16* __restrict__ Bl,
    int bm, int bn, int k0, uint32_t dst, int tid)
{
#pragma unroll
    for (int t = 0; t < 2; t++) {
        int u = tid + t * 256;
        int r = u >> 2;
        int c = (u & 3) * 16;
        size_t ao = (size_t)(bm + r) * GK + k0;
        size_t bo = (size_t)(bn + r) * GK + k0;
        uint32_t so = (uint32_t)(r * ROWB + c);
        cp_async16(dst + so,             (const char*)(Ah + ao) + c);
        cp_async16(dst + TILEB + so,     (const char*)(Al + ao) + c);
        cp_async16(dst + 2 * TILEB + so, (const char*)(Bh + bo) + c);
        cp_async16(dst + 3 * TILEB + so, (const char*)(Bl + bo) + c);
    }
    asm volatile("cp.async.commit_group;\n" ::: "memory");
}

__device__ __forceinline__ void gemm_body(
    const __nv_bfloat16* __restrict__ A_hi, const __nv_bfloat16* __restrict__ A_lo,
    const __nv_bfloat16* __restrict__ B_hi, const __nv_bfloat16* __restrict__ B_lo,
    int bm, int bn, uint32_t sb, float acc[2][8][4])
{
    const int tid  = threadIdx.x;
    const int lane = tid & 31;
    const int w    = tid >> 5;
    const int m_off = (w & 3) * 32;
    const int n_off = (w >> 2) * 64;

#pragma unroll
    for (int mt = 0; mt < 2; mt++)
#pragma unroll
        for (int nt = 0; nt < 8; nt++)
#pragma unroll
            for (int i = 0; i < 4; i++) acc[mt][nt][i] = 0.0f;

    const uint32_t a_off = (uint32_t)((m_off + (lane & 15)) * ROWB + 16 * (lane >> 4));
    const uint32_t b_off = (uint32_t)((n_off + (lane & 7) + 8 * (lane >> 4)) * ROWB
                                      + 16 * ((lane >> 3) & 1));

    load_chunk4(A_hi, A_lo, B_hi, B_lo, bm, bn, 0,   sb,        tid);
    load_chunk4(A_hi, A_lo, B_hi, B_lo, bm, bn, GBK, sb + SETB, tid);

    for (int i = 0; i < NKCH; i++) {
        if (i + 1 < NKCH) {
            asm volatile("cp.async.wait_group 1;\n" ::: "memory");
        } else {
            asm volatile("cp.async.wait_group 0;\n" ::: "memory");
        }
        __syncthreads();

        const uint32_t base = sb + (uint32_t)(i & 1) * SETB;
#pragma unroll
        for (int ks = 0; ks < 2; ks++) {
            uint32_t ah[2][4], al[2][4];
#pragma unroll
            for (int mt = 0; mt < 2; mt++) {
                uint32_t aadr = base + a_off + (uint32_t)(mt * 16 * ROWB + ks * 32);
                ldsm_x4(ah[mt], aadr);
                ldsm_x4(al[mt], aadr + TILEB);
            }
            uint32_t b2[8][2];
#pragma unroll
            for (int np = 0; np < 4; np++) {
                uint32_t r4[4];
                ldsm_x4(r4, base + 2 * TILEB + b_off + (uint32_t)(np * 16 * ROWB + ks * 32));
                b2[2*np][0] = r4[0]; b2[2*np][1] = r4[1];
                b2[2*np+1][0] = r4[2]; b2[2*np+1][1] = r4[3];
            }
#pragma unroll
            for (int mt = 0; mt < 2; mt++)
#pragma unroll
                for (int nt = 0; nt < 8; nt++) {
                    mma_16816(acc[mt][nt], ah[mt], b2[nt]);
                    mma_16816(acc[mt][nt], al[mt], b2[nt]);
                }
#pragma unroll
            for (int np = 0; np < 4; np++) {
                uint32_t r4[4];
                ldsm_x4(r4, base + 3 * TILEB + b_off + (uint32_t)(np * 16 * ROWB + ks * 32));
                b2[2*np][0] = r4[0]; b2[2*np][1] = r4[1];
                b2[2*np+1][0] = r4[2]; b2[2*np+1][1] = r4[3];
            }
#pragma unroll
            for (int mt = 0; mt < 2; mt++)
#pragma unroll
                for (int nt = 0; nt < 8; nt++)
                    mma_16816(acc[mt][nt], ah[mt], b2[nt]);
        }
        __syncthreads();

        if (i + 2 < NKCH)
            load_chunk4(A_hi, A_lo, B_hi, B_lo, bm, bn, (i + 2) * GBK, base, tid);
    }
}

// Fused QKV: blockIdx.x in [0,24); sel = bx>>3 routes weight/output.
__global__ __launch_bounds__(256, 2) void gemm_qkv_kernel(
    const __nv_bfloat16* __restrict__ A_hi, const __nv_bfloat16* __restrict__ A_lo,
    const __nv_bfloat16* __restrict__ Wqh, const __nv_bfloat16* __restrict__ Wql,
    const __nv_bfloat16* __restrict__ Wkh, const __nv_bfloat16* __restrict__ Wkl,
    const __nv_bfloat16* __restrict__ Wvh, const __nv_bfloat16* __restrict__ Wvl,
    __nv_bfloat16* __restrict__ Qh, __nv_bfloat16* __restrict__ Ql,
    __nv_bfloat16* __restrict__ Kh, __nv_bfloat16* __restrict__ Kl,
    __nv_bfloat16* __restrict__ Vh, __nv_bfloat16* __restrict__ Vl)
{
    extern __shared__ __align__(16) char gsm[];
    const uint32_t sb = smem_u32(gsm);
    const int sel = blockIdx.x >> 3;
    const int bn  = (blockIdx.x & 7) * 128;
    const int bm  = blockIdx.y * 128;
    const __nv_bfloat16* Bh = sel == 0 ? Wqh : sel == 1 ? Wkh : Wvh;
    const __nv_bfloat16* Bl = sel == 0 ? Wql : sel == 1 ? Wkl : Wvl;
    __nv_bfloat16* Ch = sel == 0 ? Qh : sel == 1 ? Kh : Vh;
    __nv_bfloat16* Cl = sel == 0 ? Ql : sel == 1 ? Kl : Vl;

    float acc[2][8][4];
    gemm_body(A_hi, A_lo, Bh, Bl, bm, bn, sb, acc);

    const int lane = threadIdx.x & 31;
    const int w    = threadIdx.x >> 5;
    const int m_off = (w & 3) * 32;
    const int n_off = (w >> 2) * 64;
    const int g = lane >> 2;
    const int q = lane & 3;
#pragma unroll
    for (int mt = 0; mt < 2; mt++) {
#pragma unroll
        for (int nt = 0; nt < 8; nt++) {
            int row = bm + m_off + mt * 16 + g;
            int col = bn + n_off + nt * 8 + q * 2;
            uint32_t h0 = pack_bf(acc[mt][nt][0], acc[mt][nt][1]);
            uint32_t l0 = pack_bf(acc[mt][nt][0] - bf_lo(h0),
                                  acc[mt][nt][1] - bf_hi(h0));
            *(uint32_t*)(Ch + (size_t)row * D_MODEL + col) = h0;
            *(uint32_t*)(Cl + (size_t)row * D_MODEL + col) = l0;
            uint32_t h1 = pack_bf(acc[mt][nt][2], acc[mt][nt][3]);
            uint32_t l1 = pack_bf(acc[mt][nt][2] - bf_lo(h1),
                                  acc[mt][nt][3] - bf_hi(h1));
            *(uint32_t*)(Ch + (size_t)(row + 8) * D_MODEL + col) = h1;
            *(uint32_t*)(Cl + (size_t)(row + 8) * D_MODEL + col) = l1;
        }
    }
}

// Output GEMM: fp32 C
__global__ __launch_bounds__(256, 2) void gemm_out_kernel(
    const __nv_bfloat16* __restrict__ A_hi, const __nv_bfloat16* __restrict__ A_lo,
    const __nv_bfloat16* __restrict__ B_hi, const __nv_bfloat16* __restrict__ B_lo,
    float* __restrict__ Cf)
{
    extern __shared__ __align__(16) char gsm[];
    const uint32_t sb = smem_u32(gsm);
    const int bn = blockIdx.x * 128;
    const int bm = blockIdx.y * 128;

    float acc[2][8][4];
    gemm_body(A_hi, A_lo, B_hi, B_lo, bm, bn, sb, acc);

    const int lane = threadIdx.x & 31;
    const int w    = threadIdx.x >> 5;
    const int m_off = (w & 3) * 32;
    const int n_off = (w >> 2) * 64;
    const int g = lane >> 2;
    const int q = lane & 3;
#pragma unroll
    for (int mt = 0; mt < 2; mt++) {
#pragma unroll
        for (int nt = 0; nt < 8; nt++) {
            int row = bm + m_off + mt * 16 + g;
            int col = bn + n_off + nt * 8 + q * 2;
            *(float2*)(Cf + (size_t)row * D_MODEL + col) =
                make_float2(acc[mt][nt][0], acc[mt][nt][1]);
            *(float2*)(Cf + (size_t)(row + 8) * D_MODEL + col) =
                make_float2(acc[mt][nt][2], acc[mt][nt][3]);
        }
    }
}

// ---------------------------------------------------------------------------
// Tensor-core causal flash attention (FA2-style register softmax).
// CTA: 128 q-rows x one head, 8 warps x 16 rows each (low register pressure,
// no spills; 2 CTAs/SM => 16 warps/SM). 64-key tiles, double-buffered
// cp.async of K/V hi+lo. 3-term bf16 splits on scores and PV.
// ---------------------------------------------------------------------------
#define AQT 128
#define AKT 64
#define AROWB 144
#define AQ_BYTES   (128 * AROWB)       // 18432
#define AKV_BYTES  (64 * AROWB)        // 9216
#define ASET_BYTES (4 * AKV_BYTES)     // 36864
#define ASM_KV0    (2 * AQ_BYTES)      // 36864
#define ASM_TOTAL  (ASM_KV0 + 2 * ASET_BYTES)   // 110592

__device__ __forceinline__ void load_kv_tile(
    const __nv_bfloat16* __restrict__ Kh, const __nv_bfloat16* __restrict__ Kl,
    const __nv_bfloat16* __restrict__ Vh, const __nv_bfloat16* __restrict__ Vl,
    int k0, int h, uint32_t base, int tid)
{
#pragma unroll
    for (int t = 0; t < 8; t++) {
        const __nv_bfloat16* src = (t < 2) ? Kh : (t < 4) ? Kl : (t < 6) ? Vh : Vl;
        int v = (t & 1) * 256 + tid;        // 0..511
        int r = v >> 3, c = v & 7;
        cp_async16(base + (t >> 1) * AKV_BYTES + r * AROWB + c * 16,
                   src + (size_t)(k0 + r) * D_MODEL + h * D_K + c * 8);
    }
    asm volatile("cp.async.commit_group;\n" ::: "memory");
}

__global__ __launch_bounds__(256, 2) void flash_mma_kernel(
    const __nv_bfloat16* __restrict__ Qh, const __nv_bfloat16* __restrict__ Ql,
    const __nv_bfloat16* __restrict__ Kh, const __nv_bfloat16* __restrict__ Kl,
    const __nv_bfloat16* __restrict__ Vh, const __nv_bfloat16* __restrict__ Vl,
    __nv_bfloat16* __restrict__ Ch, __nv_bfloat16* __restrict__ Cl)
{
    extern __shared__ char smem[];
    const uint32_t sb = smem_u32(smem);
    const int tid  = threadIdx.x;
    const int lane = tid & 31;
    const int wid  = tid >> 5;
    const int m_off = wid * 16;          // 8 warps x 16 rows
    const int h  = blockIdx.y;
    const int q0 = (int)(gridDim.x - 1 - blockIdx.x) * AQT;   // heavy blocks first
    const int g  = lane >> 2;
    const int qd = lane & 3;

    // Stage Q (hi at +0, lo at +AQ_BYTES): 8 x 16B per thread
#pragma unroll
    for (int t = 0; t < 8; t++) {
        const __nv_bfloat16* src = (t < 4) ? Qh : Ql;
        int v = (t & 3) * 256 + tid;        // 0..1023
        int r = v >> 3, c = v & 7;
        cp_async16(sb + (t >> 2) * AQ_BYTES + r * AROWB + c * 16,
                   src + (size_t)(q0 + r) * D_MODEL + h * D_K + c * 8);
    }
    asm volatile("cp.async.commit_group;\n" ::: "memory");

    const int ntiles = q0 / AKT + 2;
    load_kv_tile(Kh, Kl, Vh, Vl, 0, h, sb + ASM_KV0, tid);

    float m_i[2] = { -1e30f, -1e30f };
    float l_i[2] = { 0.f, 0.f };
    float O[8][4];
#pragma unroll
    for (int no = 0; no < 8; no++)
#pragma unroll
        for (int i = 0; i < 4; i++) O[no][i] = 0.f;

    const float C1 = 0.18033688011112042f;   // log2(e) / sqrt(64)

    // per-thread fragment offsets (tile-invariant)
    const uint32_t q_base = sb + (uint32_t)((m_off + (lane & 15)) * AROWB + 16 * (lane >> 4));
    const uint32_t k_base = (uint32_t)(((lane & 7) + 8 * (lane >> 4)) * AROWB
                                       + 16 * ((lane >> 3) & 1));
    const uint32_t v_base = (uint32_t)(((lane & 7) + 8 * ((lane >> 3) & 1)) * AROWB
                                       + 16 * (lane >> 4));

    for (int t = 0; t < ntiles; t++) {
        const uint32_t kvb = sb + ASM_KV0 + (uint32_t)(t & 1) * ASET_BYTES;
        if (t + 1 < ntiles) {
            load_kv_tile(Kh, Kl, Vh, Vl, (t + 1) * AKT, h,
                         sb + ASM_KV0 + (uint32_t)((t + 1) & 1) * ASET_BYTES, tid);
            asm volatile("cp.async.wait_group 1;\n" ::: "memory");
        } else {
            asm volatile("cp.async.wait_group 0;\n" ::: "memory");
        }
        __syncthreads();

        const int k0 = t * AKT;

        // ---- scores S[8][4] (16 q-rows x 64 keys), 3-term split ----
        float S[8][4];
#pragma unroll
        for (int nt = 0; nt < 8; nt++)
#pragma unroll
            for (int i = 0; i < 4; i++) S[nt][i] = 0.f;

#pragma unroll
        for (int ks = 0; ks < 4; ks++) {
            uint32_t qa[4], qla[4];
            uint32_t qaddr = q_base + (uint32_t)(ks * 32);
            ldsm_x4(qa, qaddr);
            ldsm_x4(qla, qaddr + AQ_BYTES);

            uint32_t b2[8][2];
#pragma unroll
            for (int np = 0; np < 4; np++) {
                uint32_t r4[4];
                ldsm_x4(r4, kvb + k_base + (uint32_t)(np * 16 * AROWB + ks * 32));
                b2[2*np][0] = r4[0]; b2[2*np][1] = r4[1];
                b2[2*np+1][0] = r4[2]; b2[2*np+1][1] = r4[3];
            }
#pragma unroll
            for (int nt = 0; nt < 8; nt++) {
                mma_16816(S[nt], qa,  b2[nt]);
                mma_16816(S[nt], qla, b2[nt]);
            }
#pragma unroll
            for (int np = 0; np < 4; np++) {
                uint32_t r4[4];
                ldsm_x4(r4, kvb + AKV_BYTES + k_base + (uint32_t)(np * 16 * AROWB + ks * 32));
                b2[2*np][0] = r4[0]; b2[2*np][1] = r4[1];
                b2[2*np+1][0] = r4[2]; b2[2*np+1][1] = r4[3];
            }
#pragma unroll
            for (int nt = 0; nt < 8; nt++)
                mma_16816(S[nt], qa, b2[nt]);
        }

        // ---- causal mask (last two tiles of each block only) ----
        if (k0 + AKT > q0) {
            int qg0 = q0 + m_off + g;
#pragma unroll
            for (int nt = 0; nt < 8; nt++) {
                int kg = k0 + nt * 8 + 2 * qd;
                if (kg     > qg0)     S[nt][0] = -1e30f;
                if (kg + 1 > qg0)     S[nt][1] = -1e30f;
                if (kg     > qg0 + 8) S[nt][2] = -1e30f;
                if (kg + 1 > qg0 + 8) S[nt][3] = -1e30f;
            }
        }

        // ---- online softmax per row half (rows g and g+8) ----
#pragma unroll
        for (int hf = 0; hf < 2; hf++) {
            float mx = -1e30f;
#pragma unroll
            for (int nt = 0; nt < 8; nt++)
                mx = fmaxf(mx, fmaxf(S[nt][2*hf], S[nt][2*hf+1]));
            mx = fmaxf(mx, __shfl_xor_sync(0xffffffffu, mx, 1));
            mx = fmaxf(mx, __shfl_xor_sync(0xffffffffu, mx, 2));
            float mold = m_i[hf];
            float mnew = fmaxf(mold, mx);
            float f  = fast_exp2((mold - mnew) * C1);
            float nm = mnew * C1;
            float sum = 0.f;
#pragma unroll
            for (int nt = 0; nt < 8; nt++) {
                float p0 = fast_exp2(fmaf(S[nt][2*hf],   C1, -nm));
                float p1 = fast_exp2(fmaf(S[nt][2*hf+1], C1, -nm));
                S[nt][2*hf] = p0; S[nt][2*hf+1] = p1;
                sum += p0 + p1;
            }
            sum += __shfl_xor_sync(0xffffffffu, sum, 1);
            sum += __shfl_xor_sync(0xffffffffu, sum, 2);
            l_i[hf] = l_i[hf] * f + sum;
            m_i[hf] = mnew;
#pragma unroll
            for (int no = 0; no < 8; no++) {
                O[no][2*hf]   *= f;
                O[no][2*hf+1] *= f;
            }
        }

        // ---- P·V, 3-term split ----
#pragma unroll
        for (int j = 0; j < 4; j++) {
            uint32_t ph[4], pl[4];
            ph[0] = pack_bf(S[2*j][0],   S[2*j][1]);
            ph[1] = pack_bf(S[2*j][2],   S[2*j][3]);
            ph[2] = pack_bf(S[2*j+1][0], S[2*j+1][1]);
            ph[3] = pack_bf(S[2*j+1][2], S[2*j+1][3]);
            pl[0] = pack_bf(S[2*j][0]   - bf_lo(ph[0]), S[2*j][1]   - bf_hi(ph[0]));
            pl[1] = pack_bf(S[2*j][2]   - bf_lo(ph[1]), S[2*j][3]   - bf_hi(ph[1]));
            pl[2] = pack_bf(S[2*j+1][0] - bf_lo(ph[2]), S[2*j+1][1] - bf_hi(ph[2]));
            pl[3] = pack_bf(S[2*j+1][2] - bf_lo(ph[3]), S[2*j+1][3] - bf_hi(ph[3]));

            uint32_t v2[8][2];
#pragma unroll
            for (int np = 0; np < 4; np++) {
                uint32_t r4[4];
                ldsm_x4_t(r4, kvb + 2 * AKV_BYTES + v_base
                              + (uint32_t)(j * 16 * AROWB + np * 32));
                v2[2*np][0] = r4[0]; v2[2*np][1] = r4[1];
                v2[2*np+1][0] = r4[2]; v2[2*np+1][1] = r4[3];
            }
#pragma unroll
            for (int no = 0; no < 8; no++) {
                mma_16816(O[no], ph, v2[no]);
                mma_16816(O[no], pl, v2[no]);
            }
#pragma unroll
            for (int np = 0; np < 4; np++) {
                uint32_t r4[4];
                ldsm_x4_t(r4, kvb + 3 * AKV_BYTES + v_base
                              + (uint32_t)(j * 16 * AROWB + np * 32));
                v2[2*np][0] = r4[0]; v2[2*np][1] = r4[1];
                v2[2*np+1][0] = r4[2]; v2[2*np+1][1] = r4[3];
            }
#pragma unroll
            for (int no = 0; no < 8; no++)
                mma_16816(O[no], ph, v2[no]);
        }
        __syncthreads();
    }

    // ---- epilogue: normalize + write bf16 hi/lo context ----
    {
        float inv0 = 1.f / l_i[0];
        float inv1 = 1.f / l_i[1];
        int r0 = q0 + m_off + g;
#pragma unroll
        for (int no = 0; no < 8; no++) {
            int col = h * D_K + no * 8 + 2 * qd;
            float o0 = O[no][0] * inv0, o1 = O[no][1] * inv0;
            float o2 = O[no][2] * inv1, o3 = O[no][3] * inv1;
            uint32_t h0 = pack_bf(o0, o1);
            uint32_t l0 = pack_bf(o0 - bf_lo(h0), o1 - bf_hi(h0));
            *(uint32_t*)(Ch + (size_t)r0 * D_MODEL + col) = h0;
            *(uint32_t*)(Cl + (size_t)r0 * D_MODEL + col) = l0;
            uint32_t h1 = pack_bf(o2, o3);
            uint32_t l1 = pack_bf(o2 - bf_lo(h1), o3 - bf_hi(h1));
            *(uint32_t*)(Ch + (size_t)(r0 + 8) * D_MODEL + col) = h1;
            *(uint32_t*)(Cl + (size_t)(r0 + 8) * D_MODEL + col) = l1;
        }
    }
}

// ---------------------------------------------------------------------------
// Launch
// ---------------------------------------------------------------------------
extern "C" void kernel_launch(void* const* d_in, const int* in_sizes, int n_in,
                              void* d_out, int out_size)
{
    const float* x   = (const float*)d_in[0];
    const float* W_q = (const float*)d_in[1];
    const float* W_k = (const float*)d_in[2];
    const float* W_v = (const float*)d_in[3];
    const float* W_o = (const float*)d_in[4];
    float* out = (float*)d_out;

    static __nv_bfloat16* xh = nullptr;
    static __nv_bfloat16 *xl, *ch, *cl, *qh, *ql, *kh, *kl, *vh, *vl;
    static __nv_bfloat16 *wqh, *wql, *wkh, *wkl, *wvh, *wvl, *woh, *wol;
    if (xh == nullptr) {
        cudaGetSymbolAddress((void**)&xl, g_xl);
        cudaGetSymbolAddress((void**)&ch, g_ch);
        cudaGetSymbolAddress((void**)&cl, g_cl);
        cudaGetSymbolAddress((void**)&qh, g_Qh);
        cudaGetSymbolAddress((void**)&ql, g_Ql);
        cudaGetSymbolAddress((void**)&kh, g_Kh);
        cudaGetSymbolAddress((void**)&kl, g_Kl);
        cudaGetSymbolAddress((void**)&vh, g_Vh);
        cudaGetSymbolAddress((void**)&vl, g_Vl);
        cudaGetSymbolAddress((void**)&wqh, g_wqh);
        cudaGetSymbolAddress((void**)&wql, g_wql);
        cudaGetSymbolAddress((void**)&wkh, g_wkh);
        cudaGetSymbolAddress((void**)&wkl, g_wkl);
        cudaGetSymbolAddress((void**)&wvh, g_wvh);
        cudaGetSymbolAddress((void**)&wvl, g_wvl);
        cudaGetSymbolAddress((void**)&woh, g_woh);
        cudaGetSymbolAddress((void**)&wol, g_wol);
        cudaFuncSetAttribute(flash_mma_kernel,
                             cudaFuncAttributeMaxDynamicSharedMemorySize, ASM_TOTAL);
        cudaFuncSetAttribute(gemm_qkv_kernel,
                             cudaFuncAttributeMaxDynamicSharedMemorySize, GSM_TOTAL);
        cudaFuncSetAttribute(gemm_out_kernel,
                             cudaFuncAttributeMaxDynamicSharedMemorySize, GSM_TOTAL);
        cudaGetSymbolAddress((void**)&xh, g_xh);   // last: publishes init
    }

    const int n_x4 = S_LEN * D_MODEL / 4;      // 1M float4s
    split_bf16_kernel<<<(n_x4 + 255) / 256, 256>>>(x, xh, xl, n_x4);
    split_w4_kernel<<<(4 * (1 << 18)) / 256, 256>>>(
        W_q, W_k, W_v, W_o,
        wqh, wql, wkh, wkl, wvh, wvl, woh, wol);

    dim3 qkvgrid(24, 32);
    gemm_qkv_kernel<<<qkvgrid, 256, GSM_TOTAL>>>(
        xh, xl, wqh, wql, wkh, wkl, wvh, wvl,
        qh, ql, kh, kl, vh, vl);

    dim3 agrid(S_LEN / AQT, NHEADS);          // (32, 16)
    flash_mma_kernel<<<agrid, 256, ASM_TOTAL>>>(qh, ql, kh, kl, vh, vl, ch, cl);

    dim3 ogrid(8, 32);
    gemm_out_kernel<<<ogrid, 256, GSM_TOTAL>>>(ch, cl, woh, wol, out);
}